// round 5
// baseline (speedup 1.0000x reference)
#include <cuda_runtime.h>
#include <math.h>

#define NE    20000
#define NR    250
#define R2    500
#define HD    256
#define TT    3
#define EE    150000
#define MM    200000
#define NNZE  320000
#define NNZR  8000
#define CH    50
#define NT    2000
#define B2    (2*NT)
#define NREP  16

// ---------------- device scratch (no allocs allowed) ----------------
__device__ float g_ent[NE*HD];
__device__ float g_rel[R2*HD];
__device__ float g_xsum[NREP*R2*HD];
__device__ float g_xcnt[R2];
__device__ float g_xin[R2*2*HD];
__device__ float g_gi[R2*3*HD];
__device__ float g_gh[R2*3*HD];
__device__ float g_entW[NE*HD];
__device__ float g_relW[R2*HD];
__device__ float g_agg[NE*HD];
__device__ float g_cnt[NE];
__device__ float g_twl[NE*HD];
__device__ float g_y[NE*HD];
__device__ float g_yrel[R2*HD];
__device__ float g_conv[(size_t)B2*CH*HD];
__device__ float g_q[B2*HD];
__device__ float g_scores[(size_t)B2*NE];
__device__ float g_nll[B2];
__device__ int   g_is64;

// ---------------- helpers ----------------
__device__ __forceinline__ int ldix(const void* p, long long i) {
    return g_is64 ? (int)((const long long*)p)[i] : ((const int*)p)[i];
}

__device__ __forceinline__ void red4(float* p, float4 v) {
    asm volatile("red.global.add.v4.f32 [%0], {%1,%2,%3,%4};"
                 :: "l"(p), "f"(v.x), "f"(v.y), "f"(v.z), "f"(v.w) : "memory");
}

__device__ __forceinline__ float sigf(float x) { return 1.0f / (1.0f + expf(-x)); }

// ---------------- small utility kernels ----------------
__global__ void detect_k(const void* p) {
    if (threadIdx.x == 0) {
        const unsigned int* w = (const unsigned int*)p;
        int is64 = 1;
        for (int i = 0; i < 8; i++) if (w[2*i+1] != 0u) is64 = 0;
        g_is64 = is64;
    }
}

__global__ void zero_k(float* p, int n) {
    int i = blockIdx.x*blockDim.x + threadIdx.x;
    if (i < n) p[i] = 0.0f;
}

__global__ void copy_k(float* d, const float* s, int n) {
    int i = blockIdx.x*blockDim.x + threadIdx.x;
    if (i < n) d[i] = s[i];
}

// histogram of r_ids (values < R2) into g_xcnt
__global__ void hist_k(const void* rids, long long off, int n) {
    __shared__ int h[R2];
    for (int i = threadIdx.x; i < R2; i += blockDim.x) h[i] = 0;
    __syncthreads();
    int stride = gridDim.x * blockDim.x;
    for (int i = blockIdx.x*blockDim.x + threadIdx.x; i < n; i += stride)
        atomicAdd(&h[ldix(rids, off + i)], 1);
    __syncthreads();
    for (int i = threadIdx.x; i < R2; i += blockDim.x)
        if (h[i]) atomicAdd(&g_xcnt[i], (float)h[i]);
}

// scatter ent rows into replicated segment accumulators
__global__ void seg_scatter_k(const void* rte, const void* rids, long long off) {
    long long idx = (long long)blockIdx.x*4 + (threadIdx.x >> 6);
    int lane = threadIdx.x & 63;
    if (idx < MM) {
        int e = ldix(rte, off + idx);
        int r = ldix(rids, off + idx);
        float4 v = ((const float4*)(g_ent + (size_t)e*HD))[lane];
        int rep = blockIdx.x & (NREP-1);
        red4(g_xsum + ((size_t)(rep*R2 + r))*HD + lane*4, v);
    }
}

// build x_in = [rel | mean]
__global__ void xin_k() {
    int i = blockIdx.x*blockDim.x + threadIdx.x;   // over R2*128 float4
    if (i >= R2*128) return;
    int row = i >> 7, c = i & 127;
    float4 v;
    if (c < 64) {
        v = ((const float4*)g_rel)[row*64 + c];
    } else {
        int c2 = c - 64;
        float4 s = make_float4(0,0,0,0);
        #pragma unroll
        for (int rep = 0; rep < NREP; rep++) {
            float4 a = ((const float4*)g_xsum)[(size_t)(rep*R2 + row)*64 + c2];
            s.x += a.x; s.y += a.y; s.z += a.z; s.w += a.w;
        }
        float inv = 1.0f / fmaxf(g_xcnt[row], 1.0f);
        v = make_float4(s.x*inv, s.y*inv, s.z*inv, s.w*inv);
    }
    ((float4*)g_xin)[i] = v;
}

// ---------------- SGEMM 128x128 tile, 8x8 per thread ----------------
// C[M,N] = A[M,K] @ (BT ? B[N,K]^T : B[K,N]) (+bias)(+relu)
// Requirements: K % 8 == 0, N % 4 == 0 (all call sites satisfy these).
template<int BT>
__global__ __launch_bounds__(256, 2)
void sgemm128_k(const float* __restrict__ A, const float* __restrict__ B,
                const float* __restrict__ bias, float* __restrict__ C,
                int M, int N, int K, int relu)
{
    __shared__ float As[8][132];   // padded: stride 132 kills stride-128 bank conflicts
    __shared__ float Bs[8][132];
    const int tid = threadIdx.x;           // 256
    const int m0 = blockIdx.y * 128, n0 = blockIdx.x * 128;
    const int tx = tid & 15, ty = tid >> 4;

    const int ar = tid >> 1;               // 0..127 (row within tile)
    const int ak = (tid & 1) * 4;          // 0 or 4

    float acc[8][8];
    #pragma unroll
    for (int i = 0; i < 8; i++)
        #pragma unroll
        for (int j = 0; j < 8; j++) acc[i][j] = 0.0f;

    for (int k0 = 0; k0 < K; k0 += 8) {
        // A tile: 128 rows x 8 k, stored transposed As[k][m]
        {
            float4 v = make_float4(0,0,0,0);
            int gm = m0 + ar;
            if (gm < M) v = *(const float4*)(A + (size_t)gm*K + k0 + ak);
            As[ak+0][ar] = v.x; As[ak+1][ar] = v.y;
            As[ak+2][ar] = v.z; As[ak+3][ar] = v.w;
        }
        if (BT) {
            // B is [N,K]; tile rows are n, k along the row
            float4 v = make_float4(0,0,0,0);
            int gn = n0 + ar;
            if (gn < N) v = *(const float4*)(B + (size_t)gn*K + k0 + ak);
            Bs[ak+0][ar] = v.x; Bs[ak+1][ar] = v.y;
            Bs[ak+2][ar] = v.z; Bs[ak+3][ar] = v.w;
        } else {
            // B is [K,N]; tile 8 k-rows x 128 n
            int bk = tid >> 5;              // 0..7
            int bn = (tid & 31) * 4;        // 0..124
            float4 v = make_float4(0,0,0,0);
            if (n0 + bn < N) v = *(const float4*)(B + (size_t)(k0+bk)*N + n0 + bn); // N%4==0
            *(float4*)&Bs[bk][bn] = v;
        }
        __syncthreads();
        #pragma unroll
        for (int k = 0; k < 8; k++) {
            float a[8], b[8];
            *(float4*)&a[0] = *(const float4*)&As[k][ty*8];
            *(float4*)&a[4] = *(const float4*)&As[k][ty*8+4];
            *(float4*)&b[0] = *(const float4*)&Bs[k][tx*8];
            *(float4*)&b[4] = *(const float4*)&Bs[k][tx*8+4];
            #pragma unroll
            for (int i = 0; i < 8; i++)
                #pragma unroll
                for (int j = 0; j < 8; j++)
                    acc[i][j] += a[i]*b[j];
        }
        __syncthreads();
    }
    // epilogue (N%4==0 so gn<N implies gn+3<N for gn%4==0)
    #pragma unroll
    for (int i = 0; i < 8; i++) {
        int gm = m0 + ty*8 + i;
        if (gm >= M) continue;
        #pragma unroll
        for (int j = 0; j < 8; j += 4) {
            int gn = n0 + tx*8 + j;
            if (gn >= N) continue;
            float4 v = make_float4(acc[i][j], acc[i][j+1], acc[i][j+2], acc[i][j+3]);
            if (bias) { v.x += bias[gn]; v.y += bias[gn+1]; v.z += bias[gn+2]; v.w += bias[gn+3]; }
            if (relu) { v.x = fmaxf(v.x,0.f); v.y = fmaxf(v.y,0.f); v.z = fmaxf(v.z,0.f); v.w = fmaxf(v.w,0.f); }
            *(float4*)(C + (size_t)gm*N + gn) = v;
        }
    }
}

// ---------------- GRU elementwise update ----------------
__global__ void gru_k() {
    int i = blockIdx.x*blockDim.x + threadIdx.x;  // over R2*64 float4
    if (i >= R2*64) return;
    int row = i >> 6, c = (i & 63) * 4;
    const float* gi = g_gi + (size_t)row*768;
    const float* gh = g_gh + (size_t)row*768;
    float4 ir = *(const float4*)(gi + c);
    float4 iz = *(const float4*)(gi + 256 + c);
    float4 in_ = *(const float4*)(gi + 512 + c);
    float4 hr = *(const float4*)(gh + c);
    float4 hz = *(const float4*)(gh + 256 + c);
    float4 hn = *(const float4*)(gh + 512 + c);
    float4 h = ((const float4*)g_rel)[i];
    float4 o;
    {
        float r = sigf(ir.x + hr.x), z = sigf(iz.x + hz.x);
        float n = tanhf(in_.x + r*hn.x);
        o.x = (1.0f - z)*n + z*h.x;
    }
    {
        float r = sigf(ir.y + hr.y), z = sigf(iz.y + hz.y);
        float n = tanhf(in_.y + r*hn.y);
        o.y = (1.0f - z)*n + z*h.y;
    }
    {
        float r = sigf(ir.z + hr.z), z = sigf(iz.z + hz.z);
        float n = tanhf(in_.z + r*hn.z);
        o.z = (1.0f - z)*n + z*h.z;
    }
    {
        float r = sigf(ir.w + hr.w), z = sigf(iz.w + hz.w);
        float n = tanhf(in_.w + r*hn.w);
        o.w = (1.0f - z)*n + z*h.w;
    }
    ((float4*)g_rel)[i] = o;
}

// ---------------- edge message scatter ----------------
__global__ void edge_scatter_k(const void* esrc, const void* erel, const void* edst, long long off) {
    long long idx = (long long)blockIdx.x*4 + (threadIdx.x >> 6);
    int lane = threadIdx.x & 63;
    if (idx < EE) {
        int s = ldix(esrc, off + idx);
        int r = ldix(erel, off + idx);
        int d = ldix(edst, off + idx);
        float4 a = ((const float4*)(g_entW + (size_t)s*HD))[lane];
        float4 b = ((const float4*)(g_relW + (size_t)r*HD))[lane];
        float4 v = make_float4(a.x+b.x, a.y+b.y, a.z+b.z, a.w+b.w);
        red4(g_agg + (size_t)d*HD + lane*4, v);
        if (lane == 0) atomicAdd(&g_cnt[d], 1.0f);
    }
}

// ---------------- gated entity update ----------------
__global__ void entupd_k() {
    int i = blockIdx.x*blockDim.x + threadIdx.x;  // over NE*64 float4
    if (i >= NE*64) return;
    int row = i >> 6;
    float inv = 1.0f / fmaxf(g_cnt[row], 1.0f);
    float4 a = ((const float4*)g_agg)[i];
    float4 cur = make_float4(fmaxf(a.x*inv, 0.f), fmaxf(a.y*inv, 0.f),
                             fmaxf(a.z*inv, 0.f), fmaxf(a.w*inv, 0.f));
    float4 tl = ((const float4*)g_twl)[i];
    float4 tw = make_float4(sigf(tl.x), sigf(tl.y), sigf(tl.z), sigf(tl.w));
    float4 e = ((const float4*)g_ent)[i];
    e.x = tw.x*cur.x + (1.0f - tw.x)*e.x;
    e.y = tw.y*cur.y + (1.0f - tw.y)*e.y;
    e.z = tw.z*cur.z + (1.0f - tw.z)*e.z;
    e.w = tw.w*cur.w + (1.0f - tw.w)*e.w;
    ((float4*)g_ent)[i] = e;
}

// ---------------- hypergraph scatter: y[row] += val * x[col] ----------------
__global__ void hyper_scatter_k(const float* x, float* y, const void* rows,
                                const void* cols, const float* val, int nnz) {
    long long idx = (long long)blockIdx.x*4 + (threadIdx.x >> 6);
    int lane = threadIdx.x & 63;
    if (idx < nnz) {
        int r = ldix(rows, idx);
        int c = ldix(cols, idx);
        float vl = val[idx];
        float4 v = ((const float4*)(x + (size_t)c*HD))[lane];
        v.x *= vl; v.y *= vl; v.z *= vl; v.w *= vl;
        red4(y + (size_t)r*HD + lane*4, v);
    }
}

// ---------------- x += l2norm(y) (per-row) ----------------
__global__ void l2add_k(float* x, const float* y) {
    int row = blockIdx.x;
    int lane = threadIdx.x;  // 64
    float4 yv = ((const float4*)(y + (size_t)row*HD))[lane];
    float ss = yv.x*yv.x + yv.y*yv.y + yv.z*yv.z + yv.w*yv.w;
    #pragma unroll
    for (int o = 16; o; o >>= 1) ss += __shfl_xor_sync(0xffffffffu, ss, o);
    __shared__ float s2[2];
    if ((lane & 31) == 0) s2[lane >> 5] = ss;
    __syncthreads();
    float nrm = sqrtf(s2[0] + s2[1]);
    float sc = 1.0f / fmaxf(nrm, 1e-12f);
    float4 xv = ((float4*)(x + (size_t)row*HD))[lane];
    xv.x += yv.x*sc; xv.y += yv.y*sc; xv.z += yv.z*sc; xv.w += yv.w*sc;
    ((float4*)(x + (size_t)row*HD))[lane] = xv;
}

// ---------------- conv1d (C_in=3, k=3, pad=1) + relu ----------------
__global__ void conv_k(const void* tt, const float* __restrict__ sent,
                       const float* __restrict__ cw, const float* __restrict__ cb) {
    int b = blockIdx.x;
    int t = threadIdx.x;  // 256 = HD
    __shared__ float sf[3][HD+2];
    __shared__ float sw[CH*9];
    __shared__ float sb[CH];
    int a0, a1, srow;
    if (b < NT) { a0 = ldix(tt, 3LL*b); a1 = ldix(tt, 3LL*b + 1); srow = b; }
    else { int i = b - NT; a0 = ldix(tt, 3LL*i + 2); a1 = ldix(tt, 3LL*i + 1) + NR; srow = i; }
    sf[0][t+1] = g_ent[(size_t)a0*HD + t];
    sf[1][t+1] = g_rel[(size_t)a1*HD + t];
    sf[2][t+1] = sent[(size_t)srow*HD + t];
    if (t < 3) { sf[t][0] = 0.0f; sf[t][HD+1] = 0.0f; }
    for (int i = t; i < CH*9; i += blockDim.x) sw[i] = cw[i];   // CH*9=450 > 256 threads
    if (t < CH) sb[t] = cb[t];
    __syncthreads();
    float v00 = sf[0][t], v01 = sf[0][t+1], v02 = sf[0][t+2];
    float v10 = sf[1][t], v11 = sf[1][t+1], v12 = sf[1][t+2];
    float v20 = sf[2][t], v21 = sf[2][t+1], v22 = sf[2][t+2];
    float* outb = g_conv + (size_t)b*CH*HD;
    #pragma unroll 5
    for (int ch = 0; ch < CH; ch++) {
        const float* w = sw + ch*9;
        float acc = sb[ch];
        acc += v00*w[0] + v01*w[1] + v02*w[2];
        acc += v10*w[3] + v11*w[4] + v12*w[5];
        acc += v20*w[6] + v21*w[7] + v22*w[8];
        outb[ch*HD + t] = fmaxf(acc, 0.0f);
    }
}

// ---------------- logsumexp NLL per test row ----------------
__global__ void lse_k(const void* tt) {
    int b = blockIdx.x;
    int tx = threadIdx.x;
    const float* row = g_scores + (size_t)b*NE;
    __shared__ float sm[256];
    float mx = -1e30f;
    for (int i = tx; i < NE; i += 256) mx = fmaxf(mx, row[i]);
    sm[tx] = mx; __syncthreads();
    for (int o = 128; o; o >>= 1) { if (tx < o) sm[tx] = fmaxf(sm[tx], sm[tx+o]); __syncthreads(); }
    float mv = sm[0];
    __syncthreads();
    float s = 0.0f;
    for (int i = tx; i < NE; i += 256) s += expf(row[i] - mv);
    sm[tx] = s; __syncthreads();
    for (int o = 128; o; o >>= 1) { if (tx < o) sm[tx] += sm[tx+o]; __syncthreads(); }
    if (tx == 0) {
        int tgt = (b < NT) ? ldix(tt, 3LL*b + 2) : ldix(tt, 3LL*(b - NT));
        g_nll[b] = mv + logf(sm[0]) - row[tgt];
    }
}

__global__ void mean_k(float* out) {
    __shared__ float sm[256];
    float s = 0.0f;
    for (int i = threadIdx.x; i < B2; i += 256) s += g_nll[i];
    sm[threadIdx.x] = s; __syncthreads();
    for (int o = 128; o; o >>= 1) { if (threadIdx.x < o) sm[threadIdx.x] += sm[threadIdx.x+o]; __syncthreads(); }
    if (threadIdx.x == 0) out[0] = sm[0] / (float)B2;
}

// ---------------- host orchestration ----------------
static void gemm(const float* A, const float* B, const float* bias, float* C,
                 int Mn, int Nn, int Kn, bool bt, bool relu) {
    dim3 g((Nn + 127)/128, (Mn + 127)/128);
    if (bt) sgemm128_k<1><<<g, 256>>>(A, B, bias, C, Mn, Nn, Kn, relu ? 1 : 0);
    else    sgemm128_k<0><<<g, 256>>>(A, B, bias, C, Mn, Nn, Kn, relu ? 1 : 0);
}

extern "C" void kernel_launch(void* const* d_in, const int* in_sizes, int n_in,
                              void* d_out, int out_size) {
    const float* dyn_emb = (const float*)d_in[0];
    const float* emb_rel = (const float*)d_in[1];
    const float* W_ih   = (const float*)d_in[2];
    const float* W_hh   = (const float*)d_in[3];
    const float* b_ih   = (const float*)d_in[4];
    const float* b_hh   = (const float*)d_in[5];
    const float* agg_W  = (const float*)d_in[6];
    const float* tg_W   = (const float*)d_in[7];
    const float* tg_b   = (const float*)d_in[8];
    const float* hev    = (const float*)d_in[9];
    const float* hrv    = (const float*)d_in[10];
    const float* conv_w = (const float*)d_in[11];
    const float* conv_b = (const float*)d_in[12];
    const float* fc_W   = (const float*)d_in[13];
    const float* fc_b   = (const float*)d_in[14];
    const float* sent   = (const float*)d_in[15];
    const void* esrc = d_in[16];
    const void* erel = d_in[17];
    const void* edst = d_in[18];
    const void* rte  = d_in[19];
    const void* rids = d_in[20];
    const void* her  = d_in[21];
    const void* hec  = d_in[22];
    const void* hrr  = d_in[23];
    const void* hrc  = d_in[24];
    const void* ttp  = d_in[25];

    float *p_ent, *p_rel, *p_xsum, *p_xcnt, *p_xin, *p_gi, *p_gh, *p_entW, *p_relW,
          *p_agg, *p_cnt, *p_twl, *p_y, *p_yrel, *p_conv, *p_q, *p_scores;
    cudaGetSymbolAddress((void**)&p_ent,  g_ent);
    cudaGetSymbolAddress((void**)&p_rel,  g_rel);
    cudaGetSymbolAddress((void**)&p_xsum, g_xsum);
    cudaGetSymbolAddress((void**)&p_xcnt, g_xcnt);
    cudaGetSymbolAddress((void**)&p_xin,  g_xin);
    cudaGetSymbolAddress((void**)&p_gi,   g_gi);
    cudaGetSymbolAddress((void**)&p_gh,   g_gh);
    cudaGetSymbolAddress((void**)&p_entW, g_entW);
    cudaGetSymbolAddress((void**)&p_relW, g_relW);
    cudaGetSymbolAddress((void**)&p_agg,  g_agg);
    cudaGetSymbolAddress((void**)&p_cnt,  g_cnt);
    cudaGetSymbolAddress((void**)&p_twl,  g_twl);
    cudaGetSymbolAddress((void**)&p_y,    g_y);
    cudaGetSymbolAddress((void**)&p_yrel, g_yrel);
    cudaGetSymbolAddress((void**)&p_conv, g_conv);
    cudaGetSymbolAddress((void**)&p_q,    g_q);
    cudaGetSymbolAddress((void**)&p_scores, g_scores);

    detect_k<<<1, 32>>>(esrc);
    copy_k<<<(NE*HD + 255)/256, 256>>>(p_ent, dyn_emb, NE*HD);
    copy_k<<<(R2*HD + 255)/256, 256>>>(p_rel, emb_rel, R2*HD);

    for (int t = 0; t < TT; t++) {
        zero_k<<<(NREP*R2*HD + 255)/256, 256>>>(p_xsum, NREP*R2*HD);
        zero_k<<<(R2 + 255)/256, 256>>>(p_xcnt, R2);
        hist_k<<<128, 256>>>(rids, (long long)t*MM, MM);
        seg_scatter_k<<<(MM + 3)/4, 256>>>(rte, rids, (long long)t*MM);
        xin_k<<<(R2*128 + 255)/256, 256>>>();
        gemm(p_xin, W_ih, b_ih, p_gi, R2, 3*HD, 2*HD, true, false);
        gemm(p_rel, W_hh, b_hh, p_gh, R2, 3*HD, HD, true, false);
        gru_k<<<(R2*64 + 255)/256, 256>>>();
        gemm(p_ent, agg_W, nullptr, p_entW, NE, HD, HD, false, false);
        gemm(p_rel, agg_W, nullptr, p_relW, R2, HD, HD, false, false);
        zero_k<<<(NE*HD + 255)/256, 256>>>(p_agg, NE*HD);
        zero_k<<<(NE + 255)/256, 256>>>(p_cnt, NE);
        edge_scatter_k<<<(EE + 3)/4, 256>>>(esrc, erel, edst, (long long)t*EE);
        gemm(p_ent, tg_W, tg_b, p_twl, NE, HD, HD, false, false);
        entupd_k<<<(NE*64 + 255)/256, 256>>>();
    }

    for (int l = 0; l < 2; l++) {
        zero_k<<<(NE*HD + 255)/256, 256>>>(p_y, NE*HD);
        hyper_scatter_k<<<(NNZE + 3)/4, 256>>>(p_ent, p_y, her, hec, hev, NNZE);
        l2add_k<<<NE, 64>>>(p_ent, p_y);
    }
    for (int l = 0; l < 2; l++) {
        zero_k<<<(R2*HD + 255)/256, 256>>>(p_yrel, R2*HD);
        hyper_scatter_k<<<(NNZR + 3)/4, 256>>>(p_rel, p_yrel, hrr, hrc, hrv, NNZR);
        l2add_k<<<R2, 64>>>(p_rel, p_yrel);
    }

    conv_k<<<B2, 256>>>(ttp, sent, conv_w, conv_b);
    gemm(p_conv, fc_W, fc_b, p_q, B2, HD, CH*HD, false, true);
    gemm(p_q, p_ent, nullptr, p_scores, B2, NE, HD, true, false);
    lse_k<<<B2, 256>>>(ttp);
    mean_k<<<1, 256>>>((float*)d_out);
}

// round 12
// speedup vs baseline: 1.0991x; 1.0991x over previous
#include <cuda_runtime.h>
#include <cuda_bf16.h>
#include <math.h>
#include <stdint.h>

#define NE    20000
#define NR    250
#define R2    500
#define HD    256
#define TT    3
#define EE    150000
#define MM    200000
#define NNZE  320000
#define NNZR  8000
#define CH    50
#define NT    2000
#define B2    (2*NT)
#define NREP  16

// ---------------- device scratch (no allocs allowed) ----------------
__device__ float g_ent[NE*HD];
__device__ float g_rel[R2*HD];
__device__ float g_xsum[NREP*R2*HD];
__device__ float g_xcnt[R2];
__device__ float g_xin[R2*2*HD];
__device__ float g_gi[R2*3*HD];
__device__ float g_gh[R2*3*HD];
__device__ float g_entW[NE*HD];
__device__ float g_relW[R2*HD];
__device__ float g_agg[NE*HD];
__device__ float g_cnt[NE];
__device__ float g_twl[NE*HD];
__device__ float g_y[NE*HD];
__device__ float g_yrel[R2*HD];
__device__ float g_conv[(size_t)B2*CH*HD];
__device__ float g_q[B2*HD];
__device__ float g_scores[(size_t)B2*NE];
__device__ float g_nll[B2];
__device__ int   g_is64;
__device__ unsigned short g_qh[B2*HD];
__device__ unsigned short g_ql[B2*HD];
__device__ unsigned short g_eh[NE*HD];
__device__ unsigned short g_el[NE*HD];

// ---------------- helpers ----------------
__device__ __forceinline__ int ldix(const void* p, long long i) {
    return g_is64 ? (int)((const long long*)p)[i] : ((const int*)p)[i];
}

__device__ __forceinline__ void red4(float* p, float4 v) {
    asm volatile("red.global.add.v4.f32 [%0], {%1,%2,%3,%4};"
                 :: "l"(p), "f"(v.x), "f"(v.y), "f"(v.z), "f"(v.w) : "memory");
}

__device__ __forceinline__ float sigf(float x) { return 1.0f / (1.0f + expf(-x)); }

// bf16 mma.sync m16n8k16 (base PTX, works on .target sm_103)
__device__ __forceinline__ void mma16816(float& c0, float& c1, float& c2, float& c3,
                                         uint32_t a0, uint32_t a1, uint32_t a2, uint32_t a3,
                                         uint32_t b0, uint32_t b1) {
    asm volatile(
        "mma.sync.aligned.m16n8k16.row.col.f32.bf16.bf16.f32 "
        "{%0,%1,%2,%3}, {%4,%5,%6,%7}, {%8,%9}, {%0,%1,%2,%3};"
        : "+f"(c0), "+f"(c1), "+f"(c2), "+f"(c3)
        : "r"(a0), "r"(a1), "r"(a2), "r"(a3), "r"(b0), "r"(b1));
}

// ---------------- small utility kernels ----------------
__global__ void detect_k(const void* p) {
    if (threadIdx.x == 0) {
        const unsigned int* w = (const unsigned int*)p;
        int is64 = 1;
        for (int i = 0; i < 8; i++) if (w[2*i+1] != 0u) is64 = 0;
        g_is64 = is64;
    }
}

__global__ void zero_k(float* p, int n) {
    int i = blockIdx.x*blockDim.x + threadIdx.x;
    if (i < n) p[i] = 0.0f;
}

__global__ void copy_k(float* d, const float* s, int n) {
    int i = blockIdx.x*blockDim.x + threadIdx.x;
    if (i < n) d[i] = s[i];
}

// split fp32 -> bf16 hi + bf16 lo
__global__ void split_k(const float* __restrict__ x, unsigned short* __restrict__ hi,
                        unsigned short* __restrict__ lo, int n) {
    int i = blockIdx.x*blockDim.x + threadIdx.x;
    if (i < n) {
        float v = x[i];
        __nv_bfloat16 h = __float2bfloat16(v);
        ((__nv_bfloat16*)hi)[i] = h;
        ((__nv_bfloat16*)lo)[i] = __float2bfloat16(v - __bfloat162float(h));
    }
}

__global__ void hist_k(const void* rids, long long off, int n) {
    __shared__ int h[R2];
    for (int i = threadIdx.x; i < R2; i += blockDim.x) h[i] = 0;
    __syncthreads();
    int stride = gridDim.x * blockDim.x;
    for (int i = blockIdx.x*blockDim.x + threadIdx.x; i < n; i += stride)
        atomicAdd(&h[ldix(rids, off + i)], 1);
    __syncthreads();
    for (int i = threadIdx.x; i < R2; i += blockDim.x)
        if (h[i]) atomicAdd(&g_xcnt[i], (float)h[i]);
}

__global__ void seg_scatter_k(const void* rte, const void* rids, long long off) {
    long long idx = (long long)blockIdx.x*4 + (threadIdx.x >> 6);
    int lane = threadIdx.x & 63;
    if (idx < MM) {
        int e = ldix(rte, off + idx);
        int r = ldix(rids, off + idx);
        float4 v = ((const float4*)(g_ent + (size_t)e*HD))[lane];
        int rep = blockIdx.x & (NREP-1);
        red4(g_xsum + ((size_t)(rep*R2 + r))*HD + lane*4, v);
    }
}

__global__ void xin_k() {
    int i = blockIdx.x*blockDim.x + threadIdx.x;
    if (i >= R2*128) return;
    int row = i >> 7, c = i & 127;
    float4 v;
    if (c < 64) {
        v = ((const float4*)g_rel)[row*64 + c];
    } else {
        int c2 = c - 64;
        float4 s = make_float4(0,0,0,0);
        #pragma unroll
        for (int rep = 0; rep < NREP; rep++) {
            float4 a = ((const float4*)g_xsum)[(size_t)(rep*R2 + row)*64 + c2];
            s.x += a.x; s.y += a.y; s.z += a.z; s.w += a.w;
        }
        float inv = 1.0f / fmaxf(g_xcnt[row], 1.0f);
        v = make_float4(s.x*inv, s.y*inv, s.z*inv, s.w*inv);
    }
    ((float4*)g_xin)[i] = v;
}

// ---------------- SGEMM 128x128 tile, 8x8 per thread ----------------
template<int BT>
__global__ __launch_bounds__(256, 2)
void sgemm128_k(const float* __restrict__ A, const float* __restrict__ B,
                const float* __restrict__ bias, float* __restrict__ C,
                int M, int N, int K, int relu)
{
    __shared__ float As[8][132];
    __shared__ float Bs[8][132];
    const int tid = threadIdx.x;
    const int tx = tid & 15, ty = tid >> 4;
    const int m0 = blockIdx.y * 128, n0 = blockIdx.x * 128;

    const int ar = tid >> 1;
    const int ak = (tid & 1) * 4;

    float acc[8][8];
    #pragma unroll
    for (int i = 0; i < 8; i++)
        #pragma unroll
        for (int j = 0; j < 8; j++) acc[i][j] = 0.0f;

    for (int k0 = 0; k0 < K; k0 += 8) {
        {
            float4 v = make_float4(0,0,0,0);
            int gm = m0 + ar;
            if (gm < M) v = *(const float4*)(A + (size_t)gm*K + k0 + ak);
            As[ak+0][ar] = v.x; As[ak+1][ar] = v.y;
            As[ak+2][ar] = v.z; As[ak+3][ar] = v.w;
        }
        if (BT) {
            float4 v = make_float4(0,0,0,0);
            int gn = n0 + ar;
            if (gn < N) v = *(const float4*)(B + (size_t)gn*K + k0 + ak);
            Bs[ak+0][ar] = v.x; Bs[ak+1][ar] = v.y;
            Bs[ak+2][ar] = v.z; Bs[ak+3][ar] = v.w;
        } else {
            int bk = tid >> 5;
            int bn = (tid & 31) * 4;
            float4 v = make_float4(0,0,0,0);
            if (n0 + bn < N) v = *(const float4*)(B + (size_t)(k0+bk)*N + n0 + bn);
            *(float4*)&Bs[bk][bn] = v;
        }
        __syncthreads();
        #pragma unroll
        for (int k = 0; k < 8; k++) {
            float a[8], b[8];
            *(float4*)&a[0] = *(const float4*)&As[k][ty*8];
            *(float4*)&a[4] = *(const float4*)&As[k][ty*8+4];
            *(float4*)&b[0] = *(const float4*)&Bs[k][tx*8];
            *(float4*)&b[4] = *(const float4*)&Bs[k][tx*8+4];
            #pragma unroll
            for (int i = 0; i < 8; i++)
                #pragma unroll
                for (int j = 0; j < 8; j++)
                    acc[i][j] += a[i]*b[j];
        }
        __syncthreads();
    }
    #pragma unroll
    for (int i = 0; i < 8; i++) {
        int gm = m0 + ty*8 + i;
        if (gm >= M) continue;
        #pragma unroll
        for (int j = 0; j < 8; j += 4) {
            int gn = n0 + tx*8 + j;
            if (gn >= N) continue;
            float4 v = make_float4(acc[i][j], acc[i][j+1], acc[i][j+2], acc[i][j+3]);
            if (bias) { v.x += bias[gn]; v.y += bias[gn+1]; v.z += bias[gn+2]; v.w += bias[gn+3]; }
            if (relu) { v.x = fmaxf(v.x,0.f); v.y = fmaxf(v.y,0.f); v.z = fmaxf(v.z,0.f); v.w = fmaxf(v.w,0.f); }
            *(float4*)(C + (size_t)gm*N + gn) = v;
        }
    }
}

// ---------------- scores GEMM via mma.sync bf16 (hi/lo split, 3 passes) -------
// scores[B2, NE] = q @ ent^T.  Block tile 128x128, 8 warps (2m x 4n), warp 64x32.
#define KC 32
#define SROW 40   // bf16 row stride: 80 B (16B-aligned, 20-word -> conflict-free)
__global__ __launch_bounds__(256)
void scores_mma_k(const unsigned short* __restrict__ qh, const unsigned short* __restrict__ ql,
                  const unsigned short* __restrict__ eh, const unsigned short* __restrict__ el,
                  float* __restrict__ out)
{
    __shared__ __nv_bfloat16 Ah[128*SROW];
    __shared__ __nv_bfloat16 Al[128*SROW];
    __shared__ __nv_bfloat16 Bh[128*SROW];
    __shared__ __nv_bfloat16 Bl[128*SROW];

    const int tid = threadIdx.x;
    const int wid = tid >> 5, lid = tid & 31;
    const int wm = wid & 1, wn = wid >> 1;     // warp tile origin: (wm*64, wn*32)
    const int m0 = blockIdx.y * 128, n0 = blockIdx.x * 128;

    float acc[4][4][4];
    #pragma unroll
    for (int i = 0; i < 4; i++)
        #pragma unroll
        for (int j = 0; j < 4; j++)
            #pragma unroll
            for (int k = 0; k < 4; k++) acc[i][j][k] = 0.0f;

    const int lrow = tid >> 1;            // 0..127
    const int lcol = (tid & 1) * 16;      // 0 or 16

    for (int k0 = 0; k0 < HD; k0 += KC) {
        // ---- G->S: 4 tiles of 128 rows x 32 bf16 ----
        {
            int gm = m0 + lrow;
            bool okA = gm < B2;
            const uint4* pa = (const uint4*)(qh + (size_t)(okA ? gm : 0)*HD + k0 + lcol);
            const uint4* pl = (const uint4*)(ql + (size_t)(okA ? gm : 0)*HD + k0 + lcol);
            uint4 z = make_uint4(0,0,0,0);
            uint4 va0 = okA ? pa[0] : z, va1 = okA ? pa[1] : z;
            uint4 vl0 = okA ? pl[0] : z, vl1 = okA ? pl[1] : z;
            uint4* da = (uint4*)&Ah[lrow*SROW + lcol];
            uint4* dl = (uint4*)&Al[lrow*SROW + lcol];
            da[0] = va0; da[1] = va1;
            dl[0] = vl0; dl[1] = vl1;

            int gn = n0 + lrow;
            bool okB = gn < NE;
            const uint4* pb = (const uint4*)(eh + (size_t)(okB ? gn : 0)*HD + k0 + lcol);
            const uint4* pe = (const uint4*)(el + (size_t)(okB ? gn : 0)*HD + k0 + lcol);
            uint4 vb0 = okB ? pb[0] : z, vb1 = okB ? pb[1] : z;
            uint4 ve0 = okB ? pe[0] : z, ve1 = okB ? pe[1] : z;
            uint4* db = (uint4*)&Bh[lrow*SROW + lcol];
            uint4* de = (uint4*)&Bl[lrow*SROW + lcol];
            db[0] = vb0; db[1] = vb1;
            de[0] = ve0; de[1] = ve1;
        }
        __syncthreads();

        // ---- 3 passes: (Ah,Bh), (Ah,Bl), (Al,Bh) ----
        #pragma unroll
        for (int pass = 0; pass < 3; pass++) {
            const __nv_bfloat16* Asrc = (pass == 2) ? Al : Ah;
            const __nv_bfloat16* Bsrc = (pass == 1) ? Bl : Bh;
            #pragma unroll
            for (int kk = 0; kk < KC; kk += 16) {
                // b-frags for 4 n-frags
                uint32_t bf[4][2];
                #pragma unroll
                for (int nf = 0; nf < 4; nf++) {
                    int nrow = wn*32 + nf*8 + (lid >> 2);
                    int kcol = kk + (lid & 3)*2;
                    bf[nf][0] = *(const uint32_t*)&Bsrc[nrow*SROW + kcol];
                    bf[nf][1] = *(const uint32_t*)&Bsrc[nrow*SROW + kcol + 8];
                }
                #pragma unroll
                for (int mf = 0; mf < 4; mf++) {
                    int mrow = wm*64 + mf*16 + (lid >> 2);
                    int kcol = kk + (lid & 3)*2;
                    uint32_t a0 = *(const uint32_t*)&Asrc[mrow*SROW + kcol];
                    uint32_t a1 = *(const uint32_t*)&Asrc[(mrow+8)*SROW + kcol];
                    uint32_t a2 = *(const uint32_t*)&Asrc[mrow*SROW + kcol + 8];
                    uint32_t a3 = *(const uint32_t*)&Asrc[(mrow+8)*SROW + kcol + 8];
                    #pragma unroll
                    for (int nf = 0; nf < 4; nf++)
                        mma16816(acc[mf][nf][0], acc[mf][nf][1], acc[mf][nf][2], acc[mf][nf][3],
                                 a0, a1, a2, a3, bf[nf][0], bf[nf][1]);
                }
            }
        }
        __syncthreads();
    }

    // ---- epilogue ----
    #pragma unroll
    for (int mf = 0; mf < 4; mf++) {
        #pragma unroll
        for (int nf = 0; nf < 4; nf++) {
            int gm = m0 + wm*64 + mf*16 + (lid >> 2);
            int gn = n0 + wn*32 + nf*8 + (lid & 3)*2;
            if (gn < NE) {
                if (gm < B2) {
                    float2 v = make_float2(acc[mf][nf][0], acc[mf][nf][1]);
                    *(float2*)(out + (size_t)gm*NE + gn) = v;
                }
                if (gm + 8 < B2) {
                    float2 v = make_float2(acc[mf][nf][2], acc[mf][nf][3]);
                    *(float2*)(out + (size_t)(gm+8)*NE + gn) = v;
                }
            }
        }
    }
}

// ---------------- GRU elementwise update ----------------
__global__ void gru_k() {
    int i = blockIdx.x*blockDim.x + threadIdx.x;
    if (i >= R2*64) return;
    int row = i >> 6, c = (i & 63) * 4;
    const float* gi = g_gi + (size_t)row*768;
    const float* gh = g_gh + (size_t)row*768;
    float4 ir = *(const float4*)(gi + c);
    float4 iz = *(const float4*)(gi + 256 + c);
    float4 in_ = *(const float4*)(gi + 512 + c);
    float4 hr = *(const float4*)(gh + c);
    float4 hz = *(const float4*)(gh + 256 + c);
    float4 hn = *(const float4*)(gh + 512 + c);
    float4 h = ((const float4*)g_rel)[i];
    float4 o;
    {
        float r = sigf(ir.x + hr.x), z = sigf(iz.x + hz.x);
        float n = tanhf(in_.x + r*hn.x);
        o.x = (1.0f - z)*n + z*h.x;
    }
    {
        float r = sigf(ir.y + hr.y), z = sigf(iz.y + hz.y);
        float n = tanhf(in_.y + r*hn.y);
        o.y = (1.0f - z)*n + z*h.y;
    }
    {
        float r = sigf(ir.z + hr.z), z = sigf(iz.z + hz.z);
        float n = tanhf(in_.z + r*hn.z);
        o.z = (1.0f - z)*n + z*h.z;
    }
    {
        float r = sigf(ir.w + hr.w), z = sigf(iz.w + hz.w);
        float n = tanhf(in_.w + r*hn.w);
        o.w = (1.0f - z)*n + z*h.w;
    }
    ((float4*)g_rel)[i] = o;
}

// ---------------- edge message scatter ----------------
__global__ void edge_scatter_k(const void* esrc, const void* erel, const void* edst, long long off) {
    long long idx = (long long)blockIdx.x*4 + (threadIdx.x >> 6);
    int lane = threadIdx.x & 63;
    if (idx < EE) {
        int s = ldix(esrc, off + idx);
        int r = ldix(erel, off + idx);
        int d = ldix(edst, off + idx);
        float4 a = ((const float4*)(g_entW + (size_t)s*HD))[lane];
        float4 b = ((const float4*)(g_relW + (size_t)r*HD))[lane];
        float4 v = make_float4(a.x+b.x, a.y+b.y, a.z+b.z, a.w+b.w);
        red4(g_agg + (size_t)d*HD + lane*4, v);
        if (lane == 0) atomicAdd(&g_cnt[d], 1.0f);
    }
}

// ---------------- gated entity update ----------------
__global__ void entupd_k() {
    int i = blockIdx.x*blockDim.x + threadIdx.x;
    if (i >= NE*64) return;
    int row = i >> 6;
    float inv = 1.0f / fmaxf(g_cnt[row], 1.0f);
    float4 a = ((const float4*)g_agg)[i];
    float4 cur = make_float4(fmaxf(a.x*inv, 0.f), fmaxf(a.y*inv, 0.f),
                             fmaxf(a.z*inv, 0.f), fmaxf(a.w*inv, 0.f));
    float4 tl = ((const float4*)g_twl)[i];
    float4 tw = make_float4(sigf(tl.x), sigf(tl.y), sigf(tl.z), sigf(tl.w));
    float4 e = ((const float4*)g_ent)[i];
    e.x = tw.x*cur.x + (1.0f - tw.x)*e.x;
    e.y = tw.y*cur.y + (1.0f - tw.y)*e.y;
    e.z = tw.z*cur.z + (1.0f - tw.z)*e.z;
    e.w = tw.w*cur.w + (1.0f - tw.w)*e.w;
    ((float4*)g_ent)[i] = e;
}

// ---------------- hypergraph scatter: y[row] += val * x[col] ----------------
__global__ void hyper_scatter_k(const float* x, float* y, const void* rows,
                                const void* cols, const float* val, int nnz) {
    long long idx = (long long)blockIdx.x*4 + (threadIdx.x >> 6);
    int lane = threadIdx.x & 63;
    if (idx < nnz) {
        int r = ldix(rows, idx);
        int c = ldix(cols, idx);
        float vl = val[idx];
        float4 v = ((const float4*)(x + (size_t)c*HD))[lane];
        v.x *= vl; v.y *= vl; v.z *= vl; v.w *= vl;
        red4(y + (size_t)r*HD + lane*4, v);
    }
}

// ---------------- x += l2norm(y) (per-row) ----------------
__global__ void l2add_k(float* x, const float* y) {
    int row = blockIdx.x;
    int lane = threadIdx.x;  // 64
    float4 yv = ((const float4*)(y + (size_t)row*HD))[lane];
    float ss = yv.x*yv.x + yv.y*yv.y + yv.z*yv.z + yv.w*yv.w;
    #pragma unroll
    for (int o = 16; o; o >>= 1) ss += __shfl_xor_sync(0xffffffffu, ss, o);
    __shared__ float s2[2];
    if ((lane & 31) == 0) s2[lane >> 5] = ss;
    __syncthreads();
    float nrm = sqrtf(s2[0] + s2[1]);
    float sc = 1.0f / fmaxf(nrm, 1e-12f);
    float4 xv = ((float4*)(x + (size_t)row*HD))[lane];
    xv.x += yv.x*sc; xv.y += yv.y*sc; xv.z += yv.z*sc; xv.w += yv.w*sc;
    ((float4*)(x + (size_t)row*HD))[lane] = xv;
}

// ---------------- conv1d (C_in=3, k=3, pad=1) + relu ----------------
__global__ void conv_k(const void* tt, const float* __restrict__ sent,
                       const float* __restrict__ cw, const float* __restrict__ cb) {
    int b = blockIdx.x;
    int t = threadIdx.x;  // 256 = HD
    __shared__ float sf[3][HD+2];
    __shared__ float sw[CH*9];
    __shared__ float sb[CH];
    int a0, a1, srow;
    if (b < NT) { a0 = ldix(tt, 3LL*b); a1 = ldix(tt, 3LL*b + 1); srow = b; }
    else { int i = b - NT; a0 = ldix(tt, 3LL*i + 2); a1 = ldix(tt, 3LL*i + 1) + NR; srow = i; }
    sf[0][t+1] = g_ent[(size_t)a0*HD + t];
    sf[1][t+1] = g_rel[(size_t)a1*HD + t];
    sf[2][t+1] = sent[(size_t)srow*HD + t];
    if (t < 3) { sf[t][0] = 0.0f; sf[t][HD+1] = 0.0f; }
    for (int i = t; i < CH*9; i += blockDim.x) sw[i] = cw[i];
    if (t < CH) sb[t] = cb[t];
    __syncthreads();
    float v00 = sf[0][t], v01 = sf[0][t+1], v02 = sf[0][t+2];
    float v10 = sf[1][t], v11 = sf[1][t+1], v12 = sf[1][t+2];
    float v20 = sf[2][t], v21 = sf[2][t+1], v22 = sf[2][t+2];
    float* outb = g_conv + (size_t)b*CH*HD;
    #pragma unroll 5
    for (int ch = 0; ch < CH; ch++) {
        const float* w = sw + ch*9;
        float acc = sb[ch];
        acc += v00*w[0] + v01*w[1] + v02*w[2];
        acc += v10*w[3] + v11*w[4] + v12*w[5];
        acc += v20*w[6] + v21*w[7] + v22*w[8];
        outb[ch*HD + t] = fmaxf(acc, 0.0f);
    }
}

// ---------------- logsumexp NLL per test row ----------------
__global__ void lse_k(const void* tt) {
    int b = blockIdx.x;
    int tx = threadIdx.x;
    const float* row = g_scores + (size_t)b*NE;
    __shared__ float sm[256];
    float mx = -1e30f;
    for (int i = tx; i < NE; i += 256) mx = fmaxf(mx, row[i]);
    sm[tx] = mx; __syncthreads();
    for (int o = 128; o; o >>= 1) { if (tx < o) sm[tx] = fmaxf(sm[tx], sm[tx+o]); __syncthreads(); }
    float mv = sm[0];
    __syncthreads();
    float s = 0.0f;
    for (int i = tx; i < NE; i += 256) s += expf(row[i] - mv);
    sm[tx] = s; __syncthreads();
    for (int o = 128; o; o >>= 1) { if (tx < o) sm[tx] += sm[tx+o]; __syncthreads(); }
    if (tx == 0) {
        int tgt = (b < NT) ? ldix(tt, 3LL*b + 2) : ldix(tt, 3LL*(b - NT));
        g_nll[b] = mv + logf(sm[0]) - row[tgt];
    }
}

__global__ void mean_k(float* out) {
    __shared__ float sm[256];
    float s = 0.0f;
    for (int i = threadIdx.x; i < B2; i += 256) s += g_nll[i];
    sm[threadIdx.x] = s; __syncthreads();
    for (int o = 128; o; o >>= 1) { if (threadIdx.x < o) sm[threadIdx.x] += sm[threadIdx.x+o]; __syncthreads(); }
    if (threadIdx.x == 0) out[0] = sm[0] / (float)B2;
}

// ---------------- host orchestration ----------------
static void gemm(const float* A, const float* B, const float* bias, float* C,
                 int Mn, int Nn, int Kn, bool bt, bool relu) {
    dim3 g((Nn + 127)/128, (Mn + 127)/128);
    if (bt) sgemm128_k<1><<<g, 256>>>(A, B, bias, C, Mn, Nn, Kn, relu ? 1 : 0);
    else    sgemm128_k<0><<<g, 256>>>(A, B, bias, C, Mn, Nn, Kn, relu ? 1 : 0);
}

extern "C" void kernel_launch(void* const* d_in, const int* in_sizes, int n_in,
                              void* d_out, int out_size) {
    const float* dyn_emb = (const float*)d_in[0];
    const float* emb_rel = (const float*)d_in[1];
    const float* W_ih   = (const float*)d_in[2];
    const float* W_hh   = (const float*)d_in[3];
    const float* b_ih   = (const float*)d_in[4];
    const float* b_hh   = (const float*)d_in[5];
    const float* agg_W  = (const float*)d_in[6];
    const float* tg_W   = (const float*)d_in[7];
    const float* tg_b   = (const float*)d_in[8];
    const float* hev    = (const float*)d_in[9];
    const float* hrv    = (const float*)d_in[10];
    const float* conv_w = (const float*)d_in[11];
    const float* conv_b = (const float*)d_in[12];
    const float* fc_W   = (const float*)d_in[13];
    const float* fc_b   = (const float*)d_in[14];
    const float* sent   = (const float*)d_in[15];
    const void* esrc = d_in[16];
    const void* erel = d_in[17];
    const void* edst = d_in[18];
    const void* rte  = d_in[19];
    const void* rids = d_in[20];
    const void* her  = d_in[21];
    const void* hec  = d_in[22];
    const void* hrr  = d_in[23];
    const void* hrc  = d_in[24];
    const void* ttp  = d_in[25];

    float *p_ent, *p_rel, *p_xsum, *p_xcnt, *p_xin, *p_gi, *p_gh, *p_entW, *p_relW,
          *p_agg, *p_cnt, *p_twl, *p_y, *p_yrel, *p_conv, *p_q, *p_scores;
    unsigned short *p_qh, *p_ql, *p_eh, *p_el;
    cudaGetSymbolAddress((void**)&p_ent,  g_ent);
    cudaGetSymbolAddress((void**)&p_rel,  g_rel);
    cudaGetSymbolAddress((void**)&p_xsum, g_xsum);
    cudaGetSymbolAddress((void**)&p_xcnt, g_xcnt);
    cudaGetSymbolAddress((void**)&p_xin,  g_xin);
    cudaGetSymbolAddress((void**)&p_gi,   g_gi);
    cudaGetSymbolAddress((void**)&p_gh,   g_gh);
    cudaGetSymbolAddress((void**)&p_entW, g_entW);
    cudaGetSymbolAddress((void**)&p_relW, g_relW);
    cudaGetSymbolAddress((void**)&p_agg,  g_agg);
    cudaGetSymbolAddress((void**)&p_cnt,  g_cnt);
    cudaGetSymbolAddress((void**)&p_twl,  g_twl);
    cudaGetSymbolAddress((void**)&p_y,    g_y);
    cudaGetSymbolAddress((void**)&p_yrel, g_yrel);
    cudaGetSymbolAddress((void**)&p_conv, g_conv);
    cudaGetSymbolAddress((void**)&p_q,    g_q);
    cudaGetSymbolAddress((void**)&p_scores, g_scores);
    cudaGetSymbolAddress((void**)&p_qh, g_qh);
    cudaGetSymbolAddress((void**)&p_ql, g_ql);
    cudaGetSymbolAddress((void**)&p_eh, g_eh);
    cudaGetSymbolAddress((void**)&p_el, g_el);

    detect_k<<<1, 32>>>(esrc);
    copy_k<<<(NE*HD + 255)/256, 256>>>(p_ent, dyn_emb, NE*HD);
    copy_k<<<(R2*HD + 255)/256, 256>>>(p_rel, emb_rel, R2*HD);

    for (int t = 0; t < TT; t++) {
        zero_k<<<(NREP*R2*HD + 255)/256, 256>>>(p_xsum, NREP*R2*HD);
        zero_k<<<(R2 + 255)/256, 256>>>(p_xcnt, R2);
        hist_k<<<128, 256>>>(rids, (long long)t*MM, MM);
        seg_scatter_k<<<(MM + 3)/4, 256>>>(rte, rids, (long long)t*MM);
        xin_k<<<(R2*128 + 255)/256, 256>>>();
        gemm(p_xin, W_ih, b_ih, p_gi, R2, 3*HD, 2*HD, true, false);
        gemm(p_rel, W_hh, b_hh, p_gh, R2, 3*HD, HD, true, false);
        gru_k<<<(R2*64 + 255)/256, 256>>>();
        gemm(p_ent, agg_W, nullptr, p_entW, NE, HD, HD, false, false);
        gemm(p_rel, agg_W, nullptr, p_relW, R2, HD, HD, false, false);
        zero_k<<<(NE*HD + 255)/256, 256>>>(p_agg, NE*HD);
        zero_k<<<(NE + 255)/256, 256>>>(p_cnt, NE);
        edge_scatter_k<<<(EE + 3)/4, 256>>>(esrc, erel, edst, (long long)t*EE);
        gemm(p_ent, tg_W, tg_b, p_twl, NE, HD, HD, false, false);
        entupd_k<<<(NE*64 + 255)/256, 256>>>();
    }

    for (int l = 0; l < 2; l++) {
        zero_k<<<(NE*HD + 255)/256, 256>>>(p_y, NE*HD);
        hyper_scatter_k<<<(NNZE + 3)/4, 256>>>(p_ent, p_y, her, hec, hev, NNZE);
        l2add_k<<<NE, 64>>>(p_ent, p_y);
    }
    for (int l = 0; l < 2; l++) {
        zero_k<<<(R2*HD + 255)/256, 256>>>(p_yrel, R2*HD);
        hyper_scatter_k<<<(NNZR + 3)/4, 256>>>(p_rel, p_yrel, hrr, hrc, hrv, NNZR);
        l2add_k<<<R2, 64>>>(p_rel, p_yrel);
    }

    // split ent/q into bf16 hi/lo for the tensor-core scores GEMM
    split_k<<<(NE*HD + 255)/256, 256>>>(p_ent, p_eh, p_el, NE*HD);

    conv_k<<<B2, 256>>>(ttp, sent, conv_w, conv_b);
    gemm(p_conv, fc_W, fc_b, p_q, B2, HD, CH*HD, false, true);
    split_k<<<(B2*HD + 255)/256, 256>>>(p_q, p_qh, p_ql, B2*HD);

    scores_mma_k<<<dim3((NE + 127)/128, (B2 + 127)/128), 256>>>(p_qh, p_ql, p_eh, p_el, p_scores);

    lse_k<<<B2, 256>>>(ttp);
    mean_k<<<1, 256>>>((float*)d_out);
}

// round 13
// speedup vs baseline: 1.6914x; 1.5389x over previous
#include <cuda_runtime.h>
#include <cuda_bf16.h>
#include <math.h>
#include <stdint.h>

#define NE    20000
#define NR    250
#define R2    500
#define HD    256
#define TT    3
#define EE    150000
#define MM    200000
#define NNZE  320000
#define NNZR  8000
#define CH    50
#define NT    2000
#define B2    (2*NT)
#define NREP  16

// ---------------- device scratch (no allocs allowed) ----------------
__device__ float g_ent[NE*HD];
__device__ float g_rel[R2*HD];
__device__ float g_xsum[NREP*R2*HD];
__device__ float g_xcnt[R2];
__device__ float g_xin[R2*2*HD];
__device__ float g_gi[R2*3*HD];
__device__ float g_gh[R2*3*HD];
__device__ float g_entW[NE*HD];
__device__ float g_relW[R2*HD];
__device__ float g_agg[NE*HD];
__device__ float g_cnt[NE];
__device__ float g_twl[NE*HD];
__device__ float g_y[NE*HD];
__device__ float g_yrel[R2*HD];
__device__ float g_q[B2*HD];
__device__ float g_scores[(size_t)B2*NE];
__device__ float g_nll[B2];
__device__ int   g_is64;
// bf16 hi/lo operand buffers
__device__ unsigned short g_qh[B2*HD];
__device__ unsigned short g_ql[B2*HD];
__device__ unsigned short g_eh[NE*HD];
__device__ unsigned short g_el[NE*HD];
__device__ unsigned short g_convh[(size_t)B2*CH*HD];
__device__ unsigned short g_convl[(size_t)B2*CH*HD];
__device__ unsigned short g_xinh[R2*2*HD];
__device__ unsigned short g_xinl[R2*2*HD];
__device__ unsigned short g_relh[R2*HD];
__device__ unsigned short g_rell[R2*HD];
__device__ unsigned short g_wihh[3*HD*2*HD];
__device__ unsigned short g_wihl[3*HD*2*HD];
__device__ unsigned short g_whhh[3*HD*HD];
__device__ unsigned short g_whhl[3*HD*HD];
__device__ unsigned short g_aggth[HD*HD];
__device__ unsigned short g_aggtl[HD*HD];
__device__ unsigned short g_tgth[HD*HD];
__device__ unsigned short g_tgtl[HD*HD];
__device__ unsigned short g_fcth[CH*HD*HD];   // [256][12800]
__device__ unsigned short g_fctl[CH*HD*HD];

// ---------------- helpers ----------------
__device__ __forceinline__ int ldix(const void* p, long long i) {
    return g_is64 ? (int)((const long long*)p)[i] : ((const int*)p)[i];
}

__device__ __forceinline__ void red4(float* p, float4 v) {
    asm volatile("red.global.add.v4.f32 [%0], {%1,%2,%3,%4};"
                 :: "l"(p), "f"(v.x), "f"(v.y), "f"(v.z), "f"(v.w) : "memory");
}

__device__ __forceinline__ float sigf(float x) { return 1.0f / (1.0f + expf(-x)); }

// bf16 mma.sync m16n8k16 (base PTX, works on .target sm_103)
__device__ __forceinline__ void mma16816(float& c0, float& c1, float& c2, float& c3,
                                         uint32_t a0, uint32_t a1, uint32_t a2, uint32_t a3,
                                         uint32_t b0, uint32_t b1) {
    asm volatile(
        "mma.sync.aligned.m16n8k16.row.col.f32.bf16.bf16.f32 "
        "{%0,%1,%2,%3}, {%4,%5,%6,%7}, {%8,%9}, {%0,%1,%2,%3};"
        : "+f"(c0), "+f"(c1), "+f"(c2), "+f"(c3)
        : "r"(a0), "r"(a1), "r"(a2), "r"(a3), "r"(b0), "r"(b1));
}

// ---------------- small utility kernels ----------------
__global__ void detect_k(const void* p) {
    if (threadIdx.x == 0) {
        const unsigned int* w = (const unsigned int*)p;
        int is64 = 1;
        for (int i = 0; i < 8; i++) if (w[2*i+1] != 0u) is64 = 0;
        g_is64 = is64;
    }
}

__global__ void zero_k(float* p, int n) {
    int i = blockIdx.x*blockDim.x + threadIdx.x;
    if (i < n) p[i] = 0.0f;
}

__global__ void copy_k(float* d, const float* s, int n) {
    int i = blockIdx.x*blockDim.x + threadIdx.x;
    if (i < n) d[i] = s[i];
}

// split fp32 -> bf16 hi + bf16 lo
__global__ void split_k(const float* __restrict__ x, unsigned short* __restrict__ hi,
                        unsigned short* __restrict__ lo, int n) {
    int i = blockIdx.x*blockDim.x + threadIdx.x;
    if (i < n) {
        float v = x[i];
        __nv_bfloat16 h = __float2bfloat16(v);
        ((__nv_bfloat16*)hi)[i] = h;
        ((__nv_bfloat16*)lo)[i] = __float2bfloat16(v - __bfloat162float(h));
    }
}

// transpose + split: x[K,N] fp32 -> hi/lo[N,K] bf16
__global__ void tsplit_k(const float* __restrict__ x, unsigned short* __restrict__ hi,
                         unsigned short* __restrict__ lo, int K, int N) {
    int i = blockIdx.x*blockDim.x + threadIdx.x;
    if (i < K*N) {
        int k = i / N, n = i % N;
        float v = x[i];
        __nv_bfloat16 h = __float2bfloat16(v);
        ((__nv_bfloat16*)hi)[(size_t)n*K + k] = h;
        ((__nv_bfloat16*)lo)[(size_t)n*K + k] = __float2bfloat16(v - __bfloat162float(h));
    }
}

__global__ void hist_k(const void* rids, long long off, int n) {
    __shared__ int h[R2];
    for (int i = threadIdx.x; i < R2; i += blockDim.x) h[i] = 0;
    __syncthreads();
    int stride = gridDim.x * blockDim.x;
    for (int i = blockIdx.x*blockDim.x + threadIdx.x; i < n; i += stride)
        atomicAdd(&h[ldix(rids, off + i)], 1);
    __syncthreads();
    for (int i = threadIdx.x; i < R2; i += blockDim.x)
        if (h[i]) atomicAdd(&g_xcnt[i], (float)h[i]);
}

__global__ void seg_scatter_k(const void* rte, const void* rids, long long off) {
    long long idx = (long long)blockIdx.x*4 + (threadIdx.x >> 6);
    int lane = threadIdx.x & 63;
    if (idx < MM) {
        int e = ldix(rte, off + idx);
        int r = ldix(rids, off + idx);
        float4 v = ((const float4*)(g_ent + (size_t)e*HD))[lane];
        int rep = blockIdx.x & (NREP-1);
        red4(g_xsum + ((size_t)(rep*R2 + r))*HD + lane*4, v);
    }
}

__global__ void xin_k() {
    int i = blockIdx.x*blockDim.x + threadIdx.x;
    if (i >= R2*128) return;
    int row = i >> 7, c = i & 127;
    float4 v;
    if (c < 64) {
        v = ((const float4*)g_rel)[row*64 + c];
    } else {
        int c2 = c - 64;
        float4 s = make_float4(0,0,0,0);
        #pragma unroll
        for (int rep = 0; rep < NREP; rep++) {
            float4 a = ((const float4*)g_xsum)[(size_t)(rep*R2 + row)*64 + c2];
            s.x += a.x; s.y += a.y; s.z += a.z; s.w += a.w;
        }
        float inv = 1.0f / fmaxf(g_xcnt[row], 1.0f);
        v = make_float4(s.x*inv, s.y*inv, s.z*inv, s.w*inv);
    }
    ((float4*)g_xin)[i] = v;
}

// ---------------- generic GEMM via mma.sync bf16 (hi/lo split, 3 passes) ------
// C[M,N] = A @ B^T (+bias)(+relu).  A: [M,K] bf16 hi/lo, B: [N,K] bf16 hi/lo.
// K % 32 == 0, N % 2 == 0.  Block tile 128x128, 8 warps (2m x 4n), warp 64x32.
#define KC 32
#define SROW 40   // bf16 row stride: 80 B (16B-aligned)
__global__ __launch_bounds__(256)
void mma_gemm_k(const unsigned short* __restrict__ Ahg, const unsigned short* __restrict__ Alg,
                const unsigned short* __restrict__ Bhg, const unsigned short* __restrict__ Blg,
                const float* __restrict__ bias, float* __restrict__ out,
                int M, int N, int K, int relu)
{
    __shared__ __nv_bfloat16 Ah[128*SROW];
    __shared__ __nv_bfloat16 Al[128*SROW];
    __shared__ __nv_bfloat16 Bh[128*SROW];
    __shared__ __nv_bfloat16 Bl[128*SROW];

    const int tid = threadIdx.x;
    const int wid = tid >> 5, lid = tid & 31;
    const int wm = wid & 1, wn = wid >> 1;
    const int m0 = blockIdx.y * 128, n0 = blockIdx.x * 128;

    float acc[4][4][4];
    #pragma unroll
    for (int i = 0; i < 4; i++)
        #pragma unroll
        for (int j = 0; j < 4; j++)
            #pragma unroll
            for (int k = 0; k < 4; k++) acc[i][j][k] = 0.0f;

    const int lrow = tid >> 1;
    const int lcol = (tid & 1) * 16;

    for (int k0 = 0; k0 < K; k0 += KC) {
        {
            int gm = m0 + lrow;
            bool okA = gm < M;
            const uint4* pa = (const uint4*)(Ahg + (size_t)(okA ? gm : 0)*K + k0 + lcol);
            const uint4* pl = (const uint4*)(Alg + (size_t)(okA ? gm : 0)*K + k0 + lcol);
            uint4 z = make_uint4(0,0,0,0);
            uint4 va0 = okA ? pa[0] : z, va1 = okA ? pa[1] : z;
            uint4 vl0 = okA ? pl[0] : z, vl1 = okA ? pl[1] : z;
            uint4* da = (uint4*)&Ah[lrow*SROW + lcol];
            uint4* dl = (uint4*)&Al[lrow*SROW + lcol];
            da[0] = va0; da[1] = va1;
            dl[0] = vl0; dl[1] = vl1;

            int gn = n0 + lrow;
            bool okB = gn < N;
            const uint4* pb = (const uint4*)(Bhg + (size_t)(okB ? gn : 0)*K + k0 + lcol);
            const uint4* pe = (const uint4*)(Blg + (size_t)(okB ? gn : 0)*K + k0 + lcol);
            uint4 vb0 = okB ? pb[0] : z, vb1 = okB ? pb[1] : z;
            uint4 ve0 = okB ? pe[0] : z, ve1 = okB ? pe[1] : z;
            uint4* db = (uint4*)&Bh[lrow*SROW + lcol];
            uint4* de = (uint4*)&Bl[lrow*SROW + lcol];
            db[0] = vb0; db[1] = vb1;
            de[0] = ve0; de[1] = ve1;
        }
        __syncthreads();

        #pragma unroll
        for (int pass = 0; pass < 3; pass++) {
            const __nv_bfloat16* Asrc = (pass == 2) ? Al : Ah;
            const __nv_bfloat16* Bsrc = (pass == 1) ? Bl : Bh;
            #pragma unroll
            for (int kk = 0; kk < KC; kk += 16) {
                uint32_t bf[4][2];
                #pragma unroll
                for (int nf = 0; nf < 4; nf++) {
                    int nrow = wn*32 + nf*8 + (lid >> 2);
                    int kcol = kk + (lid & 3)*2;
                    bf[nf][0] = *(const uint32_t*)&Bsrc[nrow*SROW + kcol];
                    bf[nf][1] = *(const uint32_t*)&Bsrc[nrow*SROW + kcol + 8];
                }
                #pragma unroll
                for (int mf = 0; mf < 4; mf++) {
                    int mrow = wm*64 + mf*16 + (lid >> 2);
                    int kcol = kk + (lid & 3)*2;
                    uint32_t a0 = *(const uint32_t*)&Asrc[mrow*SROW + kcol];
                    uint32_t a1 = *(const uint32_t*)&Asrc[(mrow+8)*SROW + kcol];
                    uint32_t a2 = *(const uint32_t*)&Asrc[mrow*SROW + kcol + 8];
                    uint32_t a3 = *(const uint32_t*)&Asrc[(mrow+8)*SROW + kcol + 8];
                    #pragma unroll
                    for (int nf = 0; nf < 4; nf++)
                        mma16816(acc[mf][nf][0], acc[mf][nf][1], acc[mf][nf][2], acc[mf][nf][3],
                                 a0, a1, a2, a3, bf[nf][0], bf[nf][1]);
                }
            }
        }
        __syncthreads();
    }

    #pragma unroll
    for (int mf = 0; mf < 4; mf++) {
        #pragma unroll
        for (int nf = 0; nf < 4; nf++) {
            int gm = m0 + wm*64 + mf*16 + (lid >> 2);
            int gn = n0 + wn*32 + nf*8 + (lid & 3)*2;
            if (gn < N) {
                float b0 = 0.0f, b1 = 0.0f;
                if (bias) { b0 = bias[gn]; b1 = bias[gn+1]; }
                if (gm < M) {
                    float2 v = make_float2(acc[mf][nf][0] + b0, acc[mf][nf][1] + b1);
                    if (relu) { v.x = fmaxf(v.x, 0.f); v.y = fmaxf(v.y, 0.f); }
                    *(float2*)(out + (size_t)gm*N + gn) = v;
                }
                if (gm + 8 < M) {
                    float2 v = make_float2(acc[mf][nf][2] + b0, acc[mf][nf][3] + b1);
                    if (relu) { v.x = fmaxf(v.x, 0.f); v.y = fmaxf(v.y, 0.f); }
                    *(float2*)(out + (size_t)(gm+8)*N + gn) = v;
                }
            }
        }
    }
}

// ---------------- GRU elementwise update ----------------
__global__ void gru_k() {
    int i = blockIdx.x*blockDim.x + threadIdx.x;
    if (i >= R2*64) return;
    int row = i >> 6, c = (i & 63) * 4;
    const float* gi = g_gi + (size_t)row*768;
    const float* gh = g_gh + (size_t)row*768;
    float4 ir = *(const float4*)(gi + c);
    float4 iz = *(const float4*)(gi + 256 + c);
    float4 in_ = *(const float4*)(gi + 512 + c);
    float4 hr = *(const float4*)(gh + c);
    float4 hz = *(const float4*)(gh + 256 + c);
    float4 hn = *(const float4*)(gh + 512 + c);
    float4 h = ((const float4*)g_rel)[i];
    float4 o;
    {
        float r = sigf(ir.x + hr.x), z = sigf(iz.x + hz.x);
        float n = tanhf(in_.x + r*hn.x);
        o.x = (1.0f - z)*n + z*h.x;
    }
    {
        float r = sigf(ir.y + hr.y), z = sigf(iz.y + hz.y);
        float n = tanhf(in_.y + r*hn.y);
        o.y = (1.0f - z)*n + z*h.y;
    }
    {
        float r = sigf(ir.z + hr.z), z = sigf(iz.z + hz.z);
        float n = tanhf(in_.z + r*hn.z);
        o.z = (1.0f - z)*n + z*h.z;
    }
    {
        float r = sigf(ir.w + hr.w), z = sigf(iz.w + hz.w);
        float n = tanhf(in_.w + r*hn.w);
        o.w = (1.0f - z)*n + z*h.w;
    }
    ((float4*)g_rel)[i] = o;
}

// ---------------- edge message scatter ----------------
__global__ void edge_scatter_k(const void* esrc, const void* erel, const void* edst, long long off) {
    long long idx = (long long)blockIdx.x*4 + (threadIdx.x >> 6);
    int lane = threadIdx.x & 63;
    if (idx < EE) {
        int s = ldix(esrc, off + idx);
        int r = ldix(erel, off + idx);
        int d = ldix(edst, off + idx);
        float4 a = ((const float4*)(g_entW + (size_t)s*HD))[lane];
        float4 b = ((const float4*)(g_relW + (size_t)r*HD))[lane];
        float4 v = make_float4(a.x+b.x, a.y+b.y, a.z+b.z, a.w+b.w);
        red4(g_agg + (size_t)d*HD + lane*4, v);
        if (lane == 0) atomicAdd(&g_cnt[d], 1.0f);
    }
}

// ---------------- gated entity update ----------------
__global__ void entupd_k() {
    int i = blockIdx.x*blockDim.x + threadIdx.x;
    if (i >= NE*64) return;
    int row = i >> 6;
    float inv = 1.0f / fmaxf(g_cnt[row], 1.0f);
    float4 a = ((const float4*)g_agg)[i];
    float4 cur = make_float4(fmaxf(a.x*inv, 0.f), fmaxf(a.y*inv, 0.f),
                             fmaxf(a.z*inv, 0.f), fmaxf(a.w*inv, 0.f));
    float4 tl = ((const float4*)g_twl)[i];
    float4 tw = make_float4(sigf(tl.x), sigf(tl.y), sigf(tl.z), sigf(tl.w));
    float4 e = ((const float4*)g_ent)[i];
    e.x = tw.x*cur.x + (1.0f - tw.x)*e.x;
    e.y = tw.y*cur.y + (1.0f - tw.y)*e.y;
    e.z = tw.z*cur.z + (1.0f - tw.z)*e.z;
    e.w = tw.w*cur.w + (1.0f - tw.w)*e.w;
    ((float4*)g_ent)[i] = e;
}

// ---------------- hypergraph scatter: y[row] += val * x[col] ----------------
__global__ void hyper_scatter_k(const float* x, float* y, const void* rows,
                                const void* cols, const float* val, int nnz) {
    long long idx = (long long)blockIdx.x*4 + (threadIdx.x >> 6);
    int lane = threadIdx.x & 63;
    if (idx < nnz) {
        int r = ldix(rows, idx);
        int c = ldix(cols, idx);
        float vl = val[idx];
        float4 v = ((const float4*)(x + (size_t)c*HD))[lane];
        v.x *= vl; v.y *= vl; v.z *= vl; v.w *= vl;
        red4(y + (size_t)r*HD + lane*4, v);
    }
}

// ---------------- x += l2norm(y) (per-row) ----------------
__global__ void l2add_k(float* x, const float* y) {
    int row = blockIdx.x;
    int lane = threadIdx.x;  // 64
    float4 yv = ((const float4*)(y + (size_t)row*HD))[lane];
    float ss = yv.x*yv.x + yv.y*yv.y + yv.z*yv.z + yv.w*yv.w;
    #pragma unroll
    for (int o = 16; o; o >>= 1) ss += __shfl_xor_sync(0xffffffffu, ss, o);
    __shared__ float s2[2];
    if ((lane & 31) == 0) s2[lane >> 5] = ss;
    __syncthreads();
    float nrm = sqrtf(s2[0] + s2[1]);
    float sc = 1.0f / fmaxf(nrm, 1e-12f);
    float4 xv = ((float4*)(x + (size_t)row*HD))[lane];
    xv.x += yv.x*sc; xv.y += yv.y*sc; xv.z += yv.z*sc; xv.w += yv.w*sc;
    ((float4*)(x + (size_t)row*HD))[lane] = xv;
}

// ---------------- conv1d (C_in=3, k=3, pad=1) + relu -> bf16 hi/lo ------------
__global__ void conv_k(const void* tt, const float* __restrict__ sent,
                       const float* __restrict__ cw, const float* __restrict__ cb) {
    int b = blockIdx.x;
    int t = threadIdx.x;  // 256 = HD
    __shared__ float sf[3][HD+2];
    __shared__ float sw[CH*9];
    __shared__ float sb[CH];
    int a0, a1, srow;
    if (b < NT) { a0 = ldix(tt, 3LL*b); a1 = ldix(tt, 3LL*b + 1); srow = b; }
    else { int i = b - NT; a0 = ldix(tt, 3LL*i + 2); a1 = ldix(tt, 3LL*i + 1) + NR; srow = i; }
    sf[0][t+1] = g_ent[(size_t)a0*HD + t];
    sf[1][t+1] = g_rel[(size_t)a1*HD + t];
    sf[2][t+1] = sent[(size_t)srow*HD + t];
    if (t < 3) { sf[t][0] = 0.0f; sf[t][HD+1] = 0.0f; }
    for (int i = t; i < CH*9; i += blockDim.x) sw[i] = cw[i];
    if (t < CH) sb[t] = cb[t];
    __syncthreads();
    float v00 = sf[0][t], v01 = sf[0][t+1], v02 = sf[0][t+2];
    float v10 = sf[1][t], v11 = sf[1][t+1], v12 = sf[1][t+2];
    float v20 = sf[2][t], v21 = sf[2][t+1], v22 = sf[2][t+2];
    size_t base = (size_t)b*CH*HD;
    #pragma unroll 5
    for (int ch = 0; ch < CH; ch++) {
        const float* w = sw + ch*9;
        float acc = sb[ch];
        acc += v00*w[0] + v01*w[1] + v02*w[2];
        acc += v10*w[3] + v11*w[4] + v12*w[5];
        acc += v20*w[6] + v21*w[7] + v22*w[8];
        acc = fmaxf(acc, 0.0f);
        __nv_bfloat16 h = __float2bfloat16(acc);
        ((__nv_bfloat16*)g_convh)[base + ch*HD + t] = h;
        ((__nv_bfloat16*)g_convl)[base + ch*HD + t] = __float2bfloat16(acc - __bfloat162float(h));
    }
}

// ---------------- logsumexp NLL per test row ----------------
__global__ void lse_k(const void* tt) {
    int b = blockIdx.x;
    int tx = threadIdx.x;
    const float* row = g_scores + (size_t)b*NE;
    __shared__ float sm[256];
    float mx = -1e30f;
    for (int i = tx; i < NE; i += 256) mx = fmaxf(mx, row[i]);
    sm[tx] = mx; __syncthreads();
    for (int o = 128; o; o >>= 1) { if (tx < o) sm[tx] = fmaxf(sm[tx], sm[tx+o]); __syncthreads(); }
    float mv = sm[0];
    __syncthreads();
    float s = 0.0f;
    for (int i = tx; i < NE; i += 256) s += expf(row[i] - mv);
    sm[tx] = s; __syncthreads();
    for (int o = 128; o; o >>= 1) { if (tx < o) sm[tx] += sm[tx+o]; __syncthreads(); }
    if (tx == 0) {
        int tgt = (b < NT) ? ldix(tt, 3LL*b + 2) : ldix(tt, 3LL*(b - NT));
        g_nll[b] = mv + logf(sm[0]) - row[tgt];
    }
}

__global__ void mean_k(float* out) {
    __shared__ float sm[256];
    float s = 0.0f;
    for (int i = threadIdx.x; i < B2; i += 256) s += g_nll[i];
    sm[threadIdx.x] = s; __syncthreads();
    for (int o = 128; o; o >>= 1) { if (threadIdx.x < o) sm[threadIdx.x] += sm[threadIdx.x+o]; __syncthreads(); }
    if (threadIdx.x == 0) out[0] = sm[0] / (float)B2;
}

// ---------------- host orchestration ----------------
static void mgemm(const unsigned short* Ah, const unsigned short* Al,
                  const unsigned short* Bh, const unsigned short* Bl,
                  const float* bias, float* C, int M, int N, int K, bool relu) {
    dim3 g((N + 127)/128, (M + 127)/128);
    mma_gemm_k<<<g, 256>>>(Ah, Al, Bh, Bl, bias, C, M, N, K, relu ? 1 : 0);
}

extern "C" void kernel_launch(void* const* d_in, const int* in_sizes, int n_in,
                              void* d_out, int out_size) {
    const float* dyn_emb = (const float*)d_in[0];
    const float* emb_rel = (const float*)d_in[1];
    const float* W_ih   = (const float*)d_in[2];
    const float* W_hh   = (const float*)d_in[3];
    const float* b_ih   = (const float*)d_in[4];
    const float* b_hh   = (const float*)d_in[5];
    const float* agg_W  = (const float*)d_in[6];
    const float* tg_W   = (const float*)d_in[7];
    const float* tg_b   = (const float*)d_in[8];
    const float* hev    = (const float*)d_in[9];
    const float* hrv    = (const float*)d_in[10];
    const float* conv_w = (const float*)d_in[11];
    const float* conv_b = (const float*)d_in[12];
    const float* fc_W   = (const float*)d_in[13];
    const float* fc_b   = (const float*)d_in[14];
    const float* sent   = (const float*)d_in[15];
    const void* esrc = d_in[16];
    const void* erel = d_in[17];
    const void* edst = d_in[18];
    const void* rte  = d_in[19];
    const void* rids = d_in[20];
    const void* her  = d_in[21];
    const void* hec  = d_in[22];
    const void* hrr  = d_in[23];
    const void* hrc  = d_in[24];
    const void* ttp  = d_in[25];

    float *p_ent, *p_rel, *p_xsum, *p_xcnt, *p_gi, *p_gh, *p_entW, *p_relW,
          *p_agg, *p_cnt, *p_twl, *p_y, *p_yrel, *p_q, *p_scores, *p_xin;
    unsigned short *p_qh, *p_ql, *p_eh, *p_el, *p_convh, *p_convl,
                   *p_xinh, *p_xinl, *p_relh, *p_rell,
                   *p_wihh, *p_wihl, *p_whhh, *p_whhl,
                   *p_aggth, *p_aggtl, *p_tgth, *p_tgtl, *p_fcth, *p_fctl;
    cudaGetSymbolAddress((void**)&p_ent,  g_ent);
    cudaGetSymbolAddress((void**)&p_rel,  g_rel);
    cudaGetSymbolAddress((void**)&p_xsum, g_xsum);
    cudaGetSymbolAddress((void**)&p_xcnt, g_xcnt);
    cudaGetSymbolAddress((void**)&p_xin,  g_xin);
    cudaGetSymbolAddress((void**)&p_gi,   g_gi);
    cudaGetSymbolAddress((void**)&p_gh,   g_gh);
    cudaGetSymbolAddress((void**)&p_entW, g_entW);
    cudaGetSymbolAddress((void**)&p_relW, g_relW);
    cudaGetSymbolAddress((void**)&p_agg,  g_agg);
    cudaGetSymbolAddress((void**)&p_cnt,  g_cnt);
    cudaGetSymbolAddress((void**)&p_twl,  g_twl);
    cudaGetSymbolAddress((void**)&p_y,    g_y);
    cudaGetSymbolAddress((void**)&p_yrel, g_yrel);
    cudaGetSymbolAddress((void**)&p_q,    g_q);
    cudaGetSymbolAddress((void**)&p_scores, g_scores);
    cudaGetSymbolAddress((void**)&p_qh, g_qh);
    cudaGetSymbolAddress((void**)&p_ql, g_ql);
    cudaGetSymbolAddress((void**)&p_eh, g_eh);
    cudaGetSymbolAddress((void**)&p_el, g_el);
    cudaGetSymbolAddress((void**)&p_convh, g_convh);
    cudaGetSymbolAddress((void**)&p_convl, g_convl);
    cudaGetSymbolAddress((void**)&p_xinh, g_xinh);
    cudaGetSymbolAddress((void**)&p_xinl, g_xinl);
    cudaGetSymbolAddress((void**)&p_relh, g_relh);
    cudaGetSymbolAddress((void**)&p_rell, g_rell);
    cudaGetSymbolAddress((void**)&p_wihh, g_wihh);
    cudaGetSymbolAddress((void**)&p_wihl, g_wihl);
    cudaGetSymbolAddress((void**)&p_whhh, g_whhh);
    cudaGetSymbolAddress((void**)&p_whhl, g_whhl);
    cudaGetSymbolAddress((void**)&p_aggth, g_aggth);
    cudaGetSymbolAddress((void**)&p_aggtl, g_aggtl);
    cudaGetSymbolAddress((void**)&p_tgth, g_tgth);
    cudaGetSymbolAddress((void**)&p_tgtl, g_tgtl);
    cudaGetSymbolAddress((void**)&p_fcth, g_fcth);
    cudaGetSymbolAddress((void**)&p_fctl, g_fctl);

    detect_k<<<1, 32>>>(esrc);
    copy_k<<<(NE*HD + 255)/256, 256>>>(p_ent, dyn_emb, NE*HD);
    copy_k<<<(R2*HD + 255)/256, 256>>>(p_rel, emb_rel, R2*HD);

    // weight preprocessing (once): split / transpose-split to bf16 hi/lo
    split_k<<<(3*HD*2*HD + 255)/256, 256>>>(W_ih, p_wihh, p_wihl, 3*HD*2*HD);   // [768,512]
    split_k<<<(3*HD*HD + 255)/256, 256>>>(W_hh, p_whhh, p_whhl, 3*HD*HD);       // [768,256]
    tsplit_k<<<(HD*HD + 255)/256, 256>>>(agg_W, p_aggth, p_aggtl, HD, HD);      // -> [256,256]
    tsplit_k<<<(HD*HD + 255)/256, 256>>>(tg_W, p_tgth, p_tgtl, HD, HD);
    tsplit_k<<<(CH*HD*HD + 255)/256, 256>>>(fc_W, p_fcth, p_fctl, CH*HD, HD);   // -> [256,12800]

    for (int t = 0; t < TT; t++) {
        zero_k<<<(NREP*R2*HD + 255)/256, 256>>>(p_xsum, NREP*R2*HD);
        zero_k<<<(R2 + 255)/256, 256>>>(p_xcnt, R2);
        hist_k<<<128, 256>>>(rids, (long long)t*MM, MM);
        seg_scatter_k<<<(MM + 3)/4, 256>>>(rte, rids, (long long)t*MM);
        xin_k<<<(R2*128 + 255)/256, 256>>>();

        // GRU gates via mma
        split_k<<<(R2*2*HD + 255)/256, 256>>>(p_xin, p_xinh, p_xinl, R2*2*HD);
        split_k<<<(R2*HD + 255)/256, 256>>>(p_rel, p_relh, p_rell, R2*HD);
        mgemm(p_xinh, p_xinl, p_wihh, p_wihl, b_ih, p_gi, R2, 3*HD, 2*HD, false);
        mgemm(p_relh, p_rell, p_whhh, p_whhl, b_hh, p_gh, R2, 3*HD, HD, false);
        gru_k<<<(R2*64 + 255)/256, 256>>>();

        // entW = ent @ agg_W ; relW = rel @ agg_W (rel is post-GRU: re-split)
        split_k<<<(NE*HD + 255)/256, 256>>>(p_ent, p_eh, p_el, NE*HD);
        split_k<<<(R2*HD + 255)/256, 256>>>(p_rel, p_relh, p_rell, R2*HD);
        mgemm(p_eh, p_el, p_aggth, p_aggtl, nullptr, p_entW, NE, HD, HD, false);
        mgemm(p_relh, p_rell, p_aggth, p_aggtl, nullptr, p_relW, R2, HD, HD, false);

        zero_k<<<(NE*HD + 255)/256, 256>>>(p_agg, NE*HD);
        zero_k<<<(NE + 255)/256, 256>>>(p_cnt, NE);
        edge_scatter_k<<<(EE + 3)/4, 256>>>(esrc, erel, edst, (long long)t*EE);

        // twl = ent @ tg_W + tg_b (same ent split)
        mgemm(p_eh, p_el, p_tgth, p_tgtl, tg_b, p_twl, NE, HD, HD, false);
        entupd_k<<<(NE*64 + 255)/256, 256>>>();
    }

    for (int l = 0; l < 2; l++) {
        zero_k<<<(NE*HD + 255)/256, 256>>>(p_y, NE*HD);
        hyper_scatter_k<<<(NNZE + 3)/4, 256>>>(p_ent, p_y, her, hec, hev, NNZE);
        l2add_k<<<NE, 64>>>(p_ent, p_y);
    }
    for (int l = 0; l < 2; l++) {
        zero_k<<<(R2*HD + 255)/256, 256>>>(p_yrel, R2*HD);
        hyper_scatter_k<<<(NNZR + 3)/4, 256>>>(p_rel, p_yrel, hrr, hrc, hrv, NNZR);
        l2add_k<<<R2, 64>>>(p_rel, p_yrel);
    }

    // final ent split for scores
    split_k<<<(NE*HD + 255)/256, 256>>>(p_ent, p_eh, p_el, NE*HD);

    conv_k<<<B2, 256>>>(ttp, sent, conv_w, conv_b);   // writes bf16 hi/lo directly
    mgemm(p_convh, p_convl, p_fcth, p_fctl, fc_b, p_q, B2, HD, CH*HD, true);
    split_k<<<(B2*HD + 255)/256, 256>>>(p_q, p_qh, p_ql, B2*HD);

    mgemm(p_qh, p_ql, p_eh, p_el, nullptr, p_scores, B2, NE, HD, false);

    lse_k<<<B2, 256>>>(ttp);
    mean_k<<<1, 256>>>((float*)d_out);
}

// round 14
// speedup vs baseline: 2.0081x; 1.1873x over previous
#include <cuda_runtime.h>
#include <cuda_bf16.h>
#include <math.h>
#include <stdint.h>

#define NE    20000
#define NR    250
#define R2    500
#define HD    256
#define TT    3
#define EE    150000
#define MM    200000
#define NNZE  320000
#define NNZR  8000
#define CH    50
#define NT    2000
#define B2    (2*NT)
#define NREP  16

// ---------------- device scratch (no allocs allowed) ----------------
__device__ float g_ent[NE*HD];
__device__ float g_rel[R2*HD];
__device__ float g_xsum[NREP*R2*HD];
__device__ float g_xcnt[R2];
__device__ float g_xin[R2*2*HD];
__device__ float g_gi[R2*3*HD];
__device__ float g_gh[R2*3*HD];
__device__ float g_entW[NE*HD];
__device__ float g_relW[R2*HD];
__device__ float g_agg[NE*HD];
__device__ float g_cnt[NE];
__device__ float g_twl[NE*HD];
__device__ float g_y[NE*HD];
__device__ float g_yrel[R2*HD];
__device__ float g_q[B2*HD];
__device__ float g_scores[(size_t)B2*NE];
__device__ float g_nll[B2];
__device__ int   g_is64;
// bf16 hi/lo operand buffers
__device__ unsigned short g_qh[B2*HD];
__device__ unsigned short g_ql[B2*HD];
__device__ unsigned short g_eh[NE*HD];
__device__ unsigned short g_el[NE*HD];
__device__ unsigned short g_convh[(size_t)B2*CH*HD];
__device__ unsigned short g_convl[(size_t)B2*CH*HD];
__device__ unsigned short g_xinh[R2*2*HD];
__device__ unsigned short g_xinl[R2*2*HD];
__device__ unsigned short g_relh[R2*HD];
__device__ unsigned short g_rell[R2*HD];
__device__ unsigned short g_wihh[3*HD*2*HD];
__device__ unsigned short g_wihl[3*HD*2*HD];
__device__ unsigned short g_whhh[3*HD*HD];
__device__ unsigned short g_whhl[3*HD*HD];
__device__ unsigned short g_aggth[HD*HD];
__device__ unsigned short g_aggtl[HD*HD];
__device__ unsigned short g_tgth[HD*HD];
__device__ unsigned short g_tgtl[HD*HD];
__device__ unsigned short g_fcth[CH*HD*HD];
__device__ unsigned short g_fctl[CH*HD*HD];

// ---------------- helpers ----------------
__device__ __forceinline__ int ldix(const void* p, long long i) {
    return g_is64 ? (int)((const long long*)p)[i] : ((const int*)p)[i];
}

__device__ __forceinline__ void red4(float* p, float4 v) {
    asm volatile("red.global.add.v4.f32 [%0], {%1,%2,%3,%4};"
                 :: "l"(p), "f"(v.x), "f"(v.y), "f"(v.z), "f"(v.w) : "memory");
}

__device__ __forceinline__ float sigf(float x) { return 1.0f / (1.0f + expf(-x)); }

__device__ __forceinline__ uint32_t s2u(const void* p) {
    uint32_t a;
    asm("{ .reg .u64 t; cvta.to.shared.u64 t, %1; cvt.u32.u64 %0, t; }" : "=r"(a) : "l"(p));
    return a;
}

// cp.async 16B with zero-fill when srcsize==0 (base PTX sm_80+)
__device__ __forceinline__ void cpa16(uint32_t dst, const void* src, int srcsize) {
    asm volatile("cp.async.ca.shared.global [%0], [%1], 16, %2;"
                 :: "r"(dst), "l"(src), "r"(srcsize) : "memory");
}
__device__ __forceinline__ void cpa_commit() { asm volatile("cp.async.commit_group;" ::: "memory"); }
__device__ __forceinline__ void cpa_wait1()  { asm volatile("cp.async.wait_group 1;" ::: "memory"); }
__device__ __forceinline__ void cpa_wait0()  { asm volatile("cp.async.wait_group 0;" ::: "memory"); }

// bf16 mma.sync m16n8k16 (base PTX, works on .target sm_103)
__device__ __forceinline__ void mma16816(float& c0, float& c1, float& c2, float& c3,
                                         uint32_t a0, uint32_t a1, uint32_t a2, uint32_t a3,
                                         uint32_t b0, uint32_t b1) {
    asm volatile(
        "mma.sync.aligned.m16n8k16.row.col.f32.bf16.bf16.f32 "
        "{%0,%1,%2,%3}, {%4,%5,%6,%7}, {%8,%9}, {%0,%1,%2,%3};"
        : "+f"(c0), "+f"(c1), "+f"(c2), "+f"(c3)
        : "r"(a0), "r"(a1), "r"(a2), "r"(a3), "r"(b0), "r"(b1));
}

// ---------------- small utility kernels ----------------
__global__ void detect_k(const void* p) {
    if (threadIdx.x == 0) {
        const unsigned int* w = (const unsigned int*)p;
        int is64 = 1;
        for (int i = 0; i < 8; i++) if (w[2*i+1] != 0u) is64 = 0;
        g_is64 = is64;
    }
}

__global__ void zero_k(float* p, int n) {
    int i = blockIdx.x*blockDim.x + threadIdx.x;
    if (i < n) p[i] = 0.0f;
}

__global__ void copy_k(float* d, const float* s, int n) {
    int i = blockIdx.x*blockDim.x + threadIdx.x;
    if (i < n) d[i] = s[i];
}

// split fp32 -> bf16 hi + bf16 lo
__global__ void split_k(const float* __restrict__ x, unsigned short* __restrict__ hi,
                        unsigned short* __restrict__ lo, int n) {
    int i = blockIdx.x*blockDim.x + threadIdx.x;
    if (i < n) {
        float v = x[i];
        __nv_bfloat16 h = __float2bfloat16(v);
        ((__nv_bfloat16*)hi)[i] = h;
        ((__nv_bfloat16*)lo)[i] = __float2bfloat16(v - __bfloat162float(h));
    }
}

// transpose + split: x[K,N] fp32 -> hi/lo[N,K] bf16
__global__ void tsplit_k(const float* __restrict__ x, unsigned short* __restrict__ hi,
                         unsigned short* __restrict__ lo, int K, int N) {
    int i = blockIdx.x*blockDim.x + threadIdx.x;
    if (i < K*N) {
        int k = i / N, n = i % N;
        float v = x[i];
        __nv_bfloat16 h = __float2bfloat16(v);
        ((__nv_bfloat16*)hi)[(size_t)n*K + k] = h;
        ((__nv_bfloat16*)lo)[(size_t)n*K + k] = __float2bfloat16(v - __bfloat162float(h));
    }
}

__global__ void hist_k(const void* rids, long long off, int n) {
    __shared__ int h[R2];
    for (int i = threadIdx.x; i < R2; i += blockDim.x) h[i] = 0;
    __syncthreads();
    int stride = gridDim.x * blockDim.x;
    for (int i = blockIdx.x*blockDim.x + threadIdx.x; i < n; i += stride)
        atomicAdd(&h[ldix(rids, off + i)], 1);
    __syncthreads();
    for (int i = threadIdx.x; i < R2; i += blockDim.x)
        if (h[i]) atomicAdd(&g_xcnt[i], (float)h[i]);
}

__global__ void seg_scatter_k(const void* rte, const void* rids, long long off) {
    long long idx = (long long)blockIdx.x*4 + (threadIdx.x >> 6);
    int lane = threadIdx.x & 63;
    if (idx < MM) {
        int e = ldix(rte, off + idx);
        int r = ldix(rids, off + idx);
        float4 v = ((const float4*)(g_ent + (size_t)e*HD))[lane];
        int rep = blockIdx.x & (NREP-1);
        red4(g_xsum + ((size_t)(rep*R2 + r))*HD + lane*4, v);
    }
}

__global__ void xin_k() {
    int i = blockIdx.x*blockDim.x + threadIdx.x;
    if (i >= R2*128) return;
    int row = i >> 7, c = i & 127;
    float4 v;
    if (c < 64) {
        v = ((const float4*)g_rel)[row*64 + c];
    } else {
        int c2 = c - 64;
        float4 s = make_float4(0,0,0,0);
        #pragma unroll
        for (int rep = 0; rep < NREP; rep++) {
            float4 a = ((const float4*)g_xsum)[(size_t)(rep*R2 + row)*64 + c2];
            s.x += a.x; s.y += a.y; s.z += a.z; s.w += a.w;
        }
        float inv = 1.0f / fmaxf(g_xcnt[row], 1.0f);
        v = make_float4(s.x*inv, s.y*inv, s.z*inv, s.w*inv);
    }
    ((float4*)g_xin)[i] = v;
}

// ---------------- generic GEMM via mma.sync bf16, cp.async double-buffered ----
// C[M,N] = A @ B^T (+bias)(+relu).  A: [M,K] bf16 hi/lo, B: [N,K] bf16 hi/lo.
// K % 32 == 0, N % 2 == 0.  Block tile 128x128, 8 warps (2m x 4n), warp 64x32.
#define KC 32
#define SROW 40                       // bf16 row stride (80 B)
#define TILE_B (128*SROW*2)           // 10240 B per tile
#define STAGE_B (4*TILE_B)            // 40960 B per stage
__global__ __launch_bounds__(256, 2)
void mma_gemm_k(const unsigned short* __restrict__ Ahg, const unsigned short* __restrict__ Alg,
                const unsigned short* __restrict__ Bhg, const unsigned short* __restrict__ Blg,
                const float* __restrict__ bias, float* __restrict__ out,
                int M, int N, int K, int relu)
{
    extern __shared__ char dynsm[];
    const uint32_t smb = s2u(dynsm);

    const int tid = threadIdx.x;
    const int wid = tid >> 5, lid = tid & 31;
    const int wm = wid & 1, wn = wid >> 1;
    const int m0 = blockIdx.y * 128, n0 = blockIdx.x * 128;

    float acc[4][4][4];
    #pragma unroll
    for (int i = 0; i < 4; i++)
        #pragma unroll
        for (int j = 0; j < 4; j++)
            #pragma unroll
            for (int k = 0; k < 4; k++) acc[i][j][k] = 0.0f;

    const int lrow = tid >> 1;            // 0..127
    const int lcol = (tid & 1) * 16;      // halves: 0 or 16 (32 B chunk = 2x16B)
    const int gmA = m0 + lrow;
    const int gnB = n0 + lrow;
    const int szA = (gmA < M) ? 16 : 0;
    const int szB = (gnB < N) ? 16 : 0;
    const int rA = (gmA < M) ? gmA : 0;
    const int rB = (gnB < N) ? gnB : 0;
    const uint32_t doff = (uint32_t)(lrow*SROW + lcol) * 2u;  // byte offset in tile

    const int niter = K / KC;

    // prefetch chunk 0 into stage 0
    {
        const int k0 = 0;
        uint32_t st = smb;
        cpa16(st + 0*TILE_B + doff,      Ahg + (size_t)rA*K + k0 + lcol,      szA);
        cpa16(st + 0*TILE_B + doff + 16, Ahg + (size_t)rA*K + k0 + lcol + 8,  szA);
        cpa16(st + 1*TILE_B + doff,      Alg + (size_t)rA*K + k0 + lcol,      szA);
        cpa16(st + 1*TILE_B + doff + 16, Alg + (size_t)rA*K + k0 + lcol + 8,  szA);
        cpa16(st + 2*TILE_B + doff,      Bhg + (size_t)rB*K + k0 + lcol,      szB);
        cpa16(st + 2*TILE_B + doff + 16, Bhg + (size_t)rB*K + k0 + lcol + 8,  szB);
        cpa16(st + 3*TILE_B + doff,      Blg + (size_t)rB*K + k0 + lcol,      szB);
        cpa16(st + 3*TILE_B + doff + 16, Blg + (size_t)rB*K + k0 + lcol + 8,  szB);
        cpa_commit();
    }

    for (int it = 0; it < niter; it++) {
        if (it + 1 < niter) {
            const int k0 = (it + 1) * KC;
            uint32_t st = smb + ((it + 1) & 1) * STAGE_B;
            cpa16(st + 0*TILE_B + doff,      Ahg + (size_t)rA*K + k0 + lcol,      szA);
            cpa16(st + 0*TILE_B + doff + 16, Ahg + (size_t)rA*K + k0 + lcol + 8,  szA);
            cpa16(st + 1*TILE_B + doff,      Alg + (size_t)rA*K + k0 + lcol,      szA);
            cpa16(st + 1*TILE_B + doff + 16, Alg + (size_t)rA*K + k0 + lcol + 8,  szA);
            cpa16(st + 2*TILE_B + doff,      Bhg + (size_t)rB*K + k0 + lcol,      szB);
            cpa16(st + 2*TILE_B + doff + 16, Bhg + (size_t)rB*K + k0 + lcol + 8,  szB);
            cpa16(st + 3*TILE_B + doff,      Blg + (size_t)rB*K + k0 + lcol,      szB);
            cpa16(st + 3*TILE_B + doff + 16, Blg + (size_t)rB*K + k0 + lcol + 8,  szB);
            cpa_commit();
            cpa_wait1();
        } else {
            cpa_wait0();
        }
        __syncthreads();

        const char* stage = dynsm + (it & 1) * STAGE_B;
        const __nv_bfloat16* Ah = (const __nv_bfloat16*)(stage + 0*TILE_B);
        const __nv_bfloat16* Al = (const __nv_bfloat16*)(stage + 1*TILE_B);
        const __nv_bfloat16* Bh = (const __nv_bfloat16*)(stage + 2*TILE_B);
        const __nv_bfloat16* Bl = (const __nv_bfloat16*)(stage + 3*TILE_B);

        #pragma unroll
        for (int pass = 0; pass < 3; pass++) {
            const __nv_bfloat16* Asrc = (pass == 2) ? Al : Ah;
            const __nv_bfloat16* Bsrc = (pass == 1) ? Bl : Bh;
            #pragma unroll
            for (int kk = 0; kk < KC; kk += 16) {
                uint32_t bf[4][2];
                #pragma unroll
                for (int nf = 0; nf < 4; nf++) {
                    int nrow = wn*32 + nf*8 + (lid >> 2);
                    int kcol = kk + (lid & 3)*2;
                    bf[nf][0] = *(const uint32_t*)&Bsrc[nrow*SROW + kcol];
                    bf[nf][1] = *(const uint32_t*)&Bsrc[nrow*SROW + kcol + 8];
                }
                #pragma unroll
                for (int mf = 0; mf < 4; mf++) {
                    int mrow = wm*64 + mf*16 + (lid >> 2);
                    int kcol = kk + (lid & 3)*2;
                    uint32_t a0 = *(const uint32_t*)&Asrc[mrow*SROW + kcol];
                    uint32_t a1 = *(const uint32_t*)&Asrc[(mrow+8)*SROW + kcol];
                    uint32_t a2 = *(const uint32_t*)&Asrc[mrow*SROW + kcol + 8];
                    uint32_t a3 = *(const uint32_t*)&Asrc[(mrow+8)*SROW + kcol + 8];
                    #pragma unroll
                    for (int nf = 0; nf < 4; nf++)
                        mma16816(acc[mf][nf][0], acc[mf][nf][1], acc[mf][nf][2], acc[mf][nf][3],
                                 a0, a1, a2, a3, bf[nf][0], bf[nf][1]);
                }
            }
        }
        __syncthreads();
    }

    #pragma unroll
    for (int mf = 0; mf < 4; mf++) {
        #pragma unroll
        for (int nf = 0; nf < 4; nf++) {
            int gm = m0 + wm*64 + mf*16 + (lid >> 2);
            int gn = n0 + wn*32 + nf*8 + (lid & 3)*2;
            if (gn < N) {
                float b0 = 0.0f, b1 = 0.0f;
                if (bias) { b0 = bias[gn]; b1 = bias[gn+1]; }
                if (gm < M) {
                    float2 v = make_float2(acc[mf][nf][0] + b0, acc[mf][nf][1] + b1);
                    if (relu) { v.x = fmaxf(v.x, 0.f); v.y = fmaxf(v.y, 0.f); }
                    *(float2*)(out + (size_t)gm*N + gn) = v;
                }
                if (gm + 8 < M) {
                    float2 v = make_float2(acc[mf][nf][2] + b0, acc[mf][nf][3] + b1);
                    if (relu) { v.x = fmaxf(v.x, 0.f); v.y = fmaxf(v.y, 0.f); }
                    *(float2*)(out + (size_t)(gm+8)*N + gn) = v;
                }
            }
        }
    }
}

// ---------------- GRU elementwise update ----------------
__global__ void gru_k() {
    int i = blockIdx.x*blockDim.x + threadIdx.x;
    if (i >= R2*64) return;
    int row = i >> 6, c = (i & 63) * 4;
    const float* gi = g_gi + (size_t)row*768;
    const float* gh = g_gh + (size_t)row*768;
    float4 ir = *(const float4*)(gi + c);
    float4 iz = *(const float4*)(gi + 256 + c);
    float4 in_ = *(const float4*)(gi + 512 + c);
    float4 hr = *(const float4*)(gh + c);
    float4 hz = *(const float4*)(gh + 256 + c);
    float4 hn = *(const float4*)(gh + 512 + c);
    float4 h = ((const float4*)g_rel)[i];
    float4 o;
    {
        float r = sigf(ir.x + hr.x), z = sigf(iz.x + hz.x);
        float n = tanhf(in_.x + r*hn.x);
        o.x = (1.0f - z)*n + z*h.x;
    }
    {
        float r = sigf(ir.y + hr.y), z = sigf(iz.y + hz.y);
        float n = tanhf(in_.y + r*hn.y);
        o.y = (1.0f - z)*n + z*h.y;
    }
    {
        float r = sigf(ir.z + hr.z), z = sigf(iz.z + hz.z);
        float n = tanhf(in_.z + r*hn.z);
        o.z = (1.0f - z)*n + z*h.z;
    }
    {
        float r = sigf(ir.w + hr.w), z = sigf(iz.w + hz.w);
        float n = tanhf(in_.w + r*hn.w);
        o.w = (1.0f - z)*n + z*h.w;
    }
    ((float4*)g_rel)[i] = o;
}

// ---------------- edge message scatter ----------------
__global__ void edge_scatter_k(const void* esrc, const void* erel, const void* edst, long long off) {
    long long idx = (long long)blockIdx.x*4 + (threadIdx.x >> 6);
    int lane = threadIdx.x & 63;
    if (idx < EE) {
        int s = ldix(esrc, off + idx);
        int r = ldix(erel, off + idx);
        int d = ldix(edst, off + idx);
        float4 a = ((const float4*)(g_entW + (size_t)s*HD))[lane];
        float4 b = ((const float4*)(g_relW + (size_t)r*HD))[lane];
        float4 v = make_float4(a.x+b.x, a.y+b.y, a.z+b.z, a.w+b.w);
        red4(g_agg + (size_t)d*HD + lane*4, v);
        if (lane == 0) atomicAdd(&g_cnt[d], 1.0f);
    }
}

// ---------------- gated entity update ----------------
__global__ void entupd_k() {
    int i = blockIdx.x*blockDim.x + threadIdx.x;
    if (i >= NE*64) return;
    int row = i >> 6;
    float inv = 1.0f / fmaxf(g_cnt[row], 1.0f);
    float4 a = ((const float4*)g_agg)[i];
    float4 cur = make_float4(fmaxf(a.x*inv, 0.f), fmaxf(a.y*inv, 0.f),
                             fmaxf(a.z*inv, 0.f), fmaxf(a.w*inv, 0.f));
    float4 tl = ((const float4*)g_twl)[i];
    float4 tw = make_float4(sigf(tl.x), sigf(tl.y), sigf(tl.z), sigf(tl.w));
    float4 e = ((const float4*)g_ent)[i];
    e.x = tw.x*cur.x + (1.0f - tw.x)*e.x;
    e.y = tw.y*cur.y + (1.0f - tw.y)*e.y;
    e.z = tw.z*cur.z + (1.0f - tw.z)*e.z;
    e.w = tw.w*cur.w + (1.0f - tw.w)*e.w;
    ((float4*)g_ent)[i] = e;
}

// ---------------- hypergraph scatter: y[row] += val * x[col] ----------------
__global__ void hyper_scatter_k(const float* x, float* y, const void* rows,
                                const void* cols, const float* val, int nnz) {
    long long idx = (long long)blockIdx.x*4 + (threadIdx.x >> 6);
    int lane = threadIdx.x & 63;
    if (idx < nnz) {
        int r = ldix(rows, idx);
        int c = ldix(cols, idx);
        float vl = val[idx];
        float4 v = ((const float4*)(x + (size_t)c*HD))[lane];
        v.x *= vl; v.y *= vl; v.z *= vl; v.w *= vl;
        red4(y + (size_t)r*HD + lane*4, v);
    }
}

// ---------------- x += l2norm(y) (per-row) ----------------
__global__ void l2add_k(float* x, const float* y) {
    int row = blockIdx.x;
    int lane = threadIdx.x;  // 64
    float4 yv = ((const float4*)(y + (size_t)row*HD))[lane];
    float ss = yv.x*yv.x + yv.y*yv.y + yv.z*yv.z + yv.w*yv.w;
    #pragma unroll
    for (int o = 16; o; o >>= 1) ss += __shfl_xor_sync(0xffffffffu, ss, o);
    __shared__ float s2[2];
    if ((lane & 31) == 0) s2[lane >> 5] = ss;
    __syncthreads();
    float nrm = sqrtf(s2[0] + s2[1]);
    float sc = 1.0f / fmaxf(nrm, 1e-12f);
    float4 xv = ((float4*)(x + (size_t)row*HD))[lane];
    xv.x += yv.x*sc; xv.y += yv.y*sc; xv.z += yv.z*sc; xv.w += yv.w*sc;
    ((float4*)(x + (size_t)row*HD))[lane] = xv;
}

// ---------------- conv1d (C_in=3, k=3, pad=1) + relu -> bf16 hi/lo ------------
__global__ void conv_k(const void* tt, const float* __restrict__ sent,
                       const float* __restrict__ cw, const float* __restrict__ cb) {
    int b = blockIdx.x;
    int t = threadIdx.x;  // 256 = HD
    __shared__ float sf[3][HD+2];
    __shared__ float sw[CH*9];
    __shared__ float sb[CH];
    int a0, a1, srow;
    if (b < NT) { a0 = ldix(tt, 3LL*b); a1 = ldix(tt, 3LL*b + 1); srow = b; }
    else { int i = b - NT; a0 = ldix(tt, 3LL*i + 2); a1 = ldix(tt, 3LL*i + 1) + NR; srow = i; }
    sf[0][t+1] = g_ent[(size_t)a0*HD + t];
    sf[1][t+1] = g_rel[(size_t)a1*HD + t];
    sf[2][t+1] = sent[(size_t)srow*HD + t];
    if (t < 3) { sf[t][0] = 0.0f; sf[t][HD+1] = 0.0f; }
    for (int i = t; i < CH*9; i += blockDim.x) sw[i] = cw[i];
    if (t < CH) sb[t] = cb[t];
    __syncthreads();
    float v00 = sf[0][t], v01 = sf[0][t+1], v02 = sf[0][t+2];
    float v10 = sf[1][t], v11 = sf[1][t+1], v12 = sf[1][t+2];
    float v20 = sf[2][t], v21 = sf[2][t+1], v22 = sf[2][t+2];
    size_t base = (size_t)b*CH*HD;
    #pragma unroll 5
    for (int ch = 0; ch < CH; ch++) {
        const float* w = sw + ch*9;
        float acc = sb[ch];
        acc += v00*w[0] + v01*w[1] + v02*w[2];
        acc += v10*w[3] + v11*w[4] + v12*w[5];
        acc += v20*w[6] + v21*w[7] + v22*w[8];
        acc = fmaxf(acc, 0.0f);
        __nv_bfloat16 h = __float2bfloat16(acc);
        ((__nv_bfloat16*)g_convh)[base + ch*HD + t] = h;
        ((__nv_bfloat16*)g_convl)[base + ch*HD + t] = __float2bfloat16(acc - __bfloat162float(h));
    }
}

// ---------------- logsumexp NLL per test row ----------------
__global__ void lse_k(const void* tt) {
    int b = blockIdx.x;
    int tx = threadIdx.x;
    const float* row = g_scores + (size_t)b*NE;
    __shared__ float sm[256];
    float mx = -1e30f;
    for (int i = tx; i < NE; i += 256) mx = fmaxf(mx, row[i]);
    sm[tx] = mx; __syncthreads();
    for (int o = 128; o; o >>= 1) { if (tx < o) sm[tx] = fmaxf(sm[tx], sm[tx+o]); __syncthreads(); }
    float mv = sm[0];
    __syncthreads();
    float s = 0.0f;
    for (int i = tx; i < NE; i += 256) s += expf(row[i] - mv);
    sm[tx] = s; __syncthreads();
    for (int o = 128; o; o >>= 1) { if (tx < o) sm[tx] += sm[tx+o]; __syncthreads(); }
    if (tx == 0) {
        int tgt = (b < NT) ? ldix(tt, 3LL*b + 2) : ldix(tt, 3LL*(b - NT));
        g_nll[b] = mv + logf(sm[0]) - row[tgt];
    }
}

__global__ void mean_k(float* out) {
    __shared__ float sm[256];
    float s = 0.0f;
    for (int i = threadIdx.x; i < B2; i += 256) s += g_nll[i];
    sm[threadIdx.x] = s; __syncthreads();
    for (int o = 128; o; o >>= 1) { if (threadIdx.x < o) sm[threadIdx.x] += sm[threadIdx.x+o]; __syncthreads(); }
    if (threadIdx.x == 0) out[0] = sm[0] / (float)B2;
}

// ---------------- host orchestration ----------------
static void mgemm(const unsigned short* Ah, const unsigned short* Al,
                  const unsigned short* Bh, const unsigned short* Bl,
                  const float* bias, float* C, int M, int N, int K, bool relu) {
    dim3 g((N + 127)/128, (M + 127)/128);
    mma_gemm_k<<<g, 256, 2*STAGE_B>>>(Ah, Al, Bh, Bl, bias, C, M, N, K, relu ? 1 : 0);
}

extern "C" void kernel_launch(void* const* d_in, const int* in_sizes, int n_in,
                              void* d_out, int out_size) {
    const float* dyn_emb = (const float*)d_in[0];
    const float* emb_rel = (const float*)d_in[1];
    const float* W_ih   = (const float*)d_in[2];
    const float* W_hh   = (const float*)d_in[3];
    const float* b_ih   = (const float*)d_in[4];
    const float* b_hh   = (const float*)d_in[5];
    const float* agg_W  = (const float*)d_in[6];
    const float* tg_W   = (const float*)d_in[7];
    const float* tg_b   = (const float*)d_in[8];
    const float* hev    = (const float*)d_in[9];
    const float* hrv    = (const float*)d_in[10];
    const float* conv_w = (const float*)d_in[11];
    const float* conv_b = (const float*)d_in[12];
    const float* fc_W   = (const float*)d_in[13];
    const float* fc_b   = (const float*)d_in[14];
    const float* sent   = (const float*)d_in[15];
    const void* esrc = d_in[16];
    const void* erel = d_in[17];
    const void* edst = d_in[18];
    const void* rte  = d_in[19];
    const void* rids = d_in[20];
    const void* her  = d_in[21];
    const void* hec  = d_in[22];
    const void* hrr  = d_in[23];
    const void* hrc  = d_in[24];
    const void* ttp  = d_in[25];

    float *p_ent, *p_rel, *p_xsum, *p_xcnt, *p_gi, *p_gh, *p_entW, *p_relW,
          *p_agg, *p_cnt, *p_twl, *p_y, *p_yrel, *p_q, *p_scores, *p_xin;
    unsigned short *p_qh, *p_ql, *p_eh, *p_el, *p_convh, *p_convl,
                   *p_xinh, *p_xinl, *p_relh, *p_rell,
                   *p_wihh, *p_wihl, *p_whhh, *p_whhl,
                   *p_aggth, *p_aggtl, *p_tgth, *p_tgtl, *p_fcth, *p_fctl;
    cudaGetSymbolAddress((void**)&p_ent,  g_ent);
    cudaGetSymbolAddress((void**)&p_rel,  g_rel);
    cudaGetSymbolAddress((void**)&p_xsum, g_xsum);
    cudaGetSymbolAddress((void**)&p_xcnt, g_xcnt);
    cudaGetSymbolAddress((void**)&p_xin,  g_xin);
    cudaGetSymbolAddress((void**)&p_gi,   g_gi);
    cudaGetSymbolAddress((void**)&p_gh,   g_gh);
    cudaGetSymbolAddress((void**)&p_entW, g_entW);
    cudaGetSymbolAddress((void**)&p_relW, g_relW);
    cudaGetSymbolAddress((void**)&p_agg,  g_agg);
    cudaGetSymbolAddress((void**)&p_cnt,  g_cnt);
    cudaGetSymbolAddress((void**)&p_twl,  g_twl);
    cudaGetSymbolAddress((void**)&p_y,    g_y);
    cudaGetSymbolAddress((void**)&p_yrel, g_yrel);
    cudaGetSymbolAddress((void**)&p_q,    g_q);
    cudaGetSymbolAddress((void**)&p_scores, g_scores);
    cudaGetSymbolAddress((void**)&p_qh, g_qh);
    cudaGetSymbolAddress((void**)&p_ql, g_ql);
    cudaGetSymbolAddress((void**)&p_eh, g_eh);
    cudaGetSymbolAddress((void**)&p_el, g_el);
    cudaGetSymbolAddress((void**)&p_convh, g_convh);
    cudaGetSymbolAddress((void**)&p_convl, g_convl);
    cudaGetSymbolAddress((void**)&p_xinh, g_xinh);
    cudaGetSymbolAddress((void**)&p_xinl, g_xinl);
    cudaGetSymbolAddress((void**)&p_relh, g_relh);
    cudaGetSymbolAddress((void**)&p_rell, g_rell);
    cudaGetSymbolAddress((void**)&p_wihh, g_wihh);
    cudaGetSymbolAddress((void**)&p_wihl, g_wihl);
    cudaGetSymbolAddress((void**)&p_whhh, g_whhh);
    cudaGetSymbolAddress((void**)&p_whhl, g_whhl);
    cudaGetSymbolAddress((void**)&p_aggth, g_aggth);
    cudaGetSymbolAddress((void**)&p_aggtl, g_aggtl);
    cudaGetSymbolAddress((void**)&p_tgth, g_tgth);
    cudaGetSymbolAddress((void**)&p_tgtl, g_tgtl);
    cudaGetSymbolAddress((void**)&p_fcth, g_fcth);
    cudaGetSymbolAddress((void**)&p_fctl, g_fctl);

    cudaFuncSetAttribute(mma_gemm_k, cudaFuncAttributeMaxDynamicSharedMemorySize, 2*STAGE_B);

    detect_k<<<1, 32>>>(esrc);
    copy_k<<<(NE*HD + 255)/256, 256>>>(p_ent, dyn_emb, NE*HD);
    copy_k<<<(R2*HD + 255)/256, 256>>>(p_rel, emb_rel, R2*HD);

    // weight preprocessing (once): split / transpose-split to bf16 hi/lo
    split_k<<<(3*HD*2*HD + 255)/256, 256>>>(W_ih, p_wihh, p_wihl, 3*HD*2*HD);
    split_k<<<(3*HD*HD + 255)/256, 256>>>(W_hh, p_whhh, p_whhl, 3*HD*HD);
    tsplit_k<<<(HD*HD + 255)/256, 256>>>(agg_W, p_aggth, p_aggtl, HD, HD);
    tsplit_k<<<(HD*HD + 255)/256, 256>>>(tg_W, p_tgth, p_tgtl, HD, HD);
    tsplit_k<<<(CH*HD*HD + 255)/256, 256>>>(fc_W, p_fcth, p_fctl, CH*HD, HD);

    for (int t = 0; t < TT; t++) {
        zero_k<<<(NREP*R2*HD + 255)/256, 256>>>(p_xsum, NREP*R2*HD);
        zero_k<<<(R2 + 255)/256, 256>>>(p_xcnt, R2);
        hist_k<<<128, 256>>>(rids, (long long)t*MM, MM);
        seg_scatter_k<<<(MM + 3)/4, 256>>>(rte, rids, (long long)t*MM);
        xin_k<<<(R2*128 + 255)/256, 256>>>();

        // GRU gates via mma
        split_k<<<(R2*2*HD + 255)/256, 256>>>(p_xin, p_xinh, p_xinl, R2*2*HD);
        split_k<<<(R2*HD + 255)/256, 256>>>(p_rel, p_relh, p_rell, R2*HD);
        mgemm(p_xinh, p_xinl, p_wihh, p_wihl, b_ih, p_gi, R2, 3*HD, 2*HD, false);
        mgemm(p_relh, p_rell, p_whhh, p_whhl, b_hh, p_gh, R2, 3*HD, HD, false);
        gru_k<<<(R2*64 + 255)/256, 256>>>();

        // entW = ent @ agg_W ; relW = rel @ agg_W (rel is post-GRU: re-split)
        split_k<<<(NE*HD + 255)/256, 256>>>(p_ent, p_eh, p_el, NE*HD);
        split_k<<<(R2*HD + 255)/256, 256>>>(p_rel, p_relh, p_rell, R2*HD);
        mgemm(p_eh, p_el, p_aggth, p_aggtl, nullptr, p_entW, NE, HD, HD, false);
        mgemm(p_relh, p_rell, p_aggth, p_aggtl, nullptr, p_relW, R2, HD, HD, false);

        zero_k<<<(NE*HD + 255)/256, 256>>>(p_agg, NE*HD);
        zero_k<<<(NE + 255)/256, 256>>>(p_cnt, NE);
        edge_scatter_k<<<(EE + 3)/4, 256>>>(esrc, erel, edst, (long long)t*EE);

        // twl = ent @ tg_W + tg_b (same ent split)
        mgemm(p_eh, p_el, p_tgth, p_tgtl, tg_b, p_twl, NE, HD, HD, false);
        entupd_k<<<(NE*64 + 255)/256, 256>>>();
    }

    for (int l = 0; l < 2; l++) {
        zero_k<<<(NE*HD + 255)/256, 256>>>(p_y, NE*HD);
        hyper_scatter_k<<<(NNZE + 3)/4, 256>>>(p_ent, p_y, her, hec, hev, NNZE);
        l2add_k<<<NE, 64>>>(p_ent, p_y);
    }
    for (int l = 0; l < 2; l++) {
        zero_k<<<(R2*HD + 255)/256, 256>>>(p_yrel, R2*HD);
        hyper_scatter_k<<<(NNZR + 3)/4, 256>>>(p_rel, p_yrel, hrr, hrc, hrv, NNZR);
        l2add_k<<<R2, 64>>>(p_rel, p_yrel);
    }

    // final ent split for scores
    split_k<<<(NE*HD + 255)/256, 256>>>(p_ent, p_eh, p_el, NE*HD);

    conv_k<<<B2, 256>>>(ttp, sent, conv_w, conv_b);   // writes bf16 hi/lo directly
    mgemm(p_convh, p_convl, p_fcth, p_fctl, fc_b, p_q, B2, HD, CH*HD, true);
    split_k<<<(B2*HD + 255)/256, 256>>>(p_q, p_qh, p_ql, B2*HD);

    mgemm(p_qh, p_ql, p_eh, p_el, nullptr, p_scores, B2, NE, HD, false);

    lse_k<<<B2, 256>>>(ttp);
    mean_k<<<1, 256>>>((float*)d_out);
}

// round 17
// speedup vs baseline: 2.0663x; 1.0289x over previous
#include <cuda_runtime.h>
#include <cuda_bf16.h>
#include <math.h>
#include <stdint.h>

#define NE    20000
#define NR    250
#define R2    500
#define HD    256
#define TT    3
#define EE    150000
#define MM    200000
#define NNZE  320000
#define NNZR  8000
#define CH    50
#define NT    2000
#define B2    (2*NT)
#define NREP  16
#define NTL   157   // ceil(NE/128) score n-tiles

// ---------------- device scratch (no allocs allowed) ----------------
__device__ float g_ent[NE*HD];
__device__ float g_rel[R2*HD];
__device__ float g_xsum[NREP*R2*HD];
__device__ float g_xcnt[R2];
__device__ float g_xin[R2*2*HD];
__device__ float g_gi[R2*3*HD];
__device__ float g_gh[R2*3*HD];
__device__ float g_entW[NE*HD];
__device__ float g_relW[R2*HD];
__device__ float g_agg[NE*HD];
__device__ float g_cnt[NE];
__device__ float g_twl[NE*HD];
__device__ float g_y[NE*HD];
__device__ float g_yrel[R2*HD];
__device__ float g_q[B2*HD];
__device__ float g_pmax[(size_t)B2*NTL];
__device__ float g_psum[(size_t)B2*NTL];
__device__ float g_nll[B2];
__device__ int   g_is64;
// bf16 hi/lo operand buffers
__device__ unsigned short g_qh[B2*HD];
__device__ unsigned short g_ql[B2*HD];
__device__ unsigned short g_eh[NE*HD];
__device__ unsigned short g_el[NE*HD];
__device__ unsigned short g_convh[(size_t)B2*CH*HD];
__device__ unsigned short g_convl[(size_t)B2*CH*HD];
__device__ unsigned short g_xinh[R2*2*HD];
__device__ unsigned short g_xinl[R2*2*HD];
__device__ unsigned short g_relh[R2*HD];
__device__ unsigned short g_rell[R2*HD];
__device__ unsigned short g_wihh[3*HD*2*HD];
__device__ unsigned short g_wihl[3*HD*2*HD];
__device__ unsigned short g_whhh[3*HD*HD];
__device__ unsigned short g_whhl[3*HD*HD];
__device__ unsigned short g_aggth[HD*HD];
__device__ unsigned short g_aggtl[HD*HD];
__device__ unsigned short g_tgth[HD*HD];
__device__ unsigned short g_tgtl[HD*HD];
__device__ unsigned short g_fcth[CH*HD*HD];
__device__ unsigned short g_fctl[CH*HD*HD];

// ---------------- helpers ----------------
__device__ __forceinline__ int ldix(const void* p, long long i) {
    return g_is64 ? (int)((const long long*)p)[i] : ((const int*)p)[i];
}

__device__ __forceinline__ void red4(float* p, float4 v) {
    asm volatile("red.global.add.v4.f32 [%0], {%1,%2,%3,%4};"
                 :: "l"(p), "f"(v.x), "f"(v.y), "f"(v.z), "f"(v.w) : "memory");
}

__device__ __forceinline__ float sigf(float x) { return 1.0f / (1.0f + expf(-x)); }

// MUFU-free exp for x <= 0 (FFMA poly on exp2): rel err ~8e-6
__device__ __forceinline__ float fexp(float x) {
    float y = x * 1.4426950408889634f;
    y = fmaxf(y, -126.0f);
    float fl = floorf(y);
    float f = y - fl;
    float p = 1.5404e-4f;
    p = p * f + 1.33336e-3f;
    p = p * f + 9.61813e-3f;
    p = p * f + 5.550411e-2f;
    p = p * f + 2.4022651e-1f;
    p = p * f + 6.9314718e-1f;
    p = p * f + 1.0f;
    int e = (int)fl;
    return p * __int_as_float((e + 127) << 23);
}

__device__ __forceinline__ uint32_t s2u(const void* p) {
    uint32_t a;
    asm("{ .reg .u64 t; cvta.to.shared.u64 t, %1; cvt.u32.u64 %0, t; }" : "=r"(a) : "l"(p));
    return a;
}

// cp.async 16B with zero-fill when srcsize==0 (base PTX sm_80+)
__device__ __forceinline__ void cpa16(uint32_t dst, const void* src, int srcsize) {
    asm volatile("cp.async.ca.shared.global [%0], [%1], 16, %2;"
                 :: "r"(dst), "l"(src), "r"(srcsize) : "memory");
}
__device__ __forceinline__ void cpa_commit() { asm volatile("cp.async.commit_group;" ::: "memory"); }
__device__ __forceinline__ void cpa_wait1()  { asm volatile("cp.async.wait_group 1;" ::: "memory"); }
__device__ __forceinline__ void cpa_wait0()  { asm volatile("cp.async.wait_group 0;" ::: "memory"); }

// bf16 mma.sync m16n8k16 (base PTX, works on .target sm_103)
__device__ __forceinline__ void mma16816(float& c0, float& c1, float& c2, float& c3,
                                         uint32_t a0, uint32_t a1, uint32_t a2, uint32_t a3,
                                         uint32_t b0, uint32_t b1) {
    asm volatile(
        "mma.sync.aligned.m16n8k16.row.col.f32.bf16.bf16.f32 "
        "{%0,%1,%2,%3}, {%4,%5,%6,%7}, {%8,%9}, {%0,%1,%2,%3};"
        : "+f"(c0), "+f"(c1), "+f"(c2), "+f"(c3)
        : "r"(a0), "r"(a1), "r"(a2), "r"(a3), "r"(b0), "r"(b1));
}

// ---------------- small utility kernels ----------------
__global__ void detect_k(const void* p) {
    if (threadIdx.x == 0) {
        const unsigned int* w = (const unsigned int*)p;
        int is64 = 1;
        for (int i = 0; i < 8; i++) if (w[2*i+1] != 0u) is64 = 0;
        g_is64 = is64;
    }
}

__global__ void zero_k(float* p, int n) {
    int i = blockIdx.x*blockDim.x + threadIdx.x;
    if (i < n) p[i] = 0.0f;
}

__global__ void copy_k(float* d, const float* s, int n) {
    int i = blockIdx.x*blockDim.x + threadIdx.x;
    if (i < n) d[i] = s[i];
}

// split fp32 -> bf16 hi + bf16 lo
__global__ void split_k(const float* __restrict__ x, unsigned short* __restrict__ hi,
                        unsigned short* __restrict__ lo, int n) {
    int i = blockIdx.x*blockDim.x + threadIdx.x;
    if (i < n) {
        float v = x[i];
        __nv_bfloat16 h = __float2bfloat16(v);
        ((__nv_bfloat16*)hi)[i] = h;
        ((__nv_bfloat16*)lo)[i] = __float2bfloat16(v - __bfloat162float(h));
    }
}

// transpose + split: x[K,N] fp32 -> hi/lo[N,K] bf16
__global__ void tsplit_k(const float* __restrict__ x, unsigned short* __restrict__ hi,
                         unsigned short* __restrict__ lo, int K, int N) {
    int i = blockIdx.x*blockDim.x + threadIdx.x;
    if (i < K*N) {
        int k = i / N, n = i % N;
        float v = x[i];
        __nv_bfloat16 h = __float2bfloat16(v);
        ((__nv_bfloat16*)hi)[(size_t)n*K + k] = h;
        ((__nv_bfloat16*)lo)[(size_t)n*K + k] = __float2bfloat16(v - __bfloat162float(h));
    }
}

__global__ void hist_k(const void* rids, long long off, int n) {
    __shared__ int h[R2];
    for (int i = threadIdx.x; i < R2; i += blockDim.x) h[i] = 0;
    __syncthreads();
    int stride = gridDim.x * blockDim.x;
    for (int i = blockIdx.x*blockDim.x + threadIdx.x; i < n; i += stride)
        atomicAdd(&h[ldix(rids, off + i)], 1);
    __syncthreads();
    for (int i = threadIdx.x; i < R2; i += blockDim.x)
        if (h[i]) atomicAdd(&g_xcnt[i], (float)h[i]);
}

__global__ void seg_scatter_k(const void* rte, const void* rids, long long off) {
    long long idx = (long long)blockIdx.x*4 + (threadIdx.x >> 6);
    int lane = threadIdx.x & 63;
    if (idx < MM) {
        int e = ldix(rte, off + idx);
        int r = ldix(rids, off + idx);
        float4 v = ((const float4*)(g_ent + (size_t)e*HD))[lane];
        int rep = blockIdx.x & (NREP-1);
        red4(g_xsum + ((size_t)(rep*R2 + r))*HD + lane*4, v);
    }
}

__global__ void xin_k() {
    int i = blockIdx.x*blockDim.x + threadIdx.x;
    if (i >= R2*128) return;
    int row = i >> 7, c = i & 127;
    float4 v;
    if (c < 64) {
        v = ((const float4*)g_rel)[row*64 + c];
    } else {
        int c2 = c - 64;
        float4 s = make_float4(0,0,0,0);
        #pragma unroll
        for (int rep = 0; rep < NREP; rep++) {
            float4 a = ((const float4*)g_xsum)[(size_t)(rep*R2 + row)*64 + c2];
            s.x += a.x; s.y += a.y; s.z += a.z; s.w += a.w;
        }
        float inv = 1.0f / fmaxf(g_xcnt[row], 1.0f);
        v = make_float4(s.x*inv, s.y*inv, s.z*inv, s.w*inv);
    }
    ((float4*)g_xin)[i] = v;
}

// ---------------- generic GEMM via mma.sync bf16, cp.async double-buffered ----
#define KC 32
#define SROW 40
#define TILE_B (128*SROW*2)
#define STAGE_B (4*TILE_B)
__global__ __launch_bounds__(256, 2)
void mma_gemm_k(const unsigned short* __restrict__ Ahg, const unsigned short* __restrict__ Alg,
                const unsigned short* __restrict__ Bhg, const unsigned short* __restrict__ Blg,
                const float* __restrict__ bias, float* __restrict__ out,
                int M, int N, int K, int relu)
{
    extern __shared__ char dynsm[];
    const uint32_t smb = s2u(dynsm);

    const int tid = threadIdx.x;
    const int wid = tid >> 5, lid = tid & 31;
    const int wm = wid & 1, wn = wid >> 1;
    const int m0 = blockIdx.y * 128, n0 = blockIdx.x * 128;

    float acc[4][4][4];
    #pragma unroll
    for (int i = 0; i < 4; i++)
        #pragma unroll
        for (int j = 0; j < 4; j++)
            #pragma unroll
            for (int k = 0; k < 4; k++) acc[i][j][k] = 0.0f;

    const int lrow = tid >> 1;
    const int lcol = (tid & 1) * 16;
    const int gmA = m0 + lrow;
    const int gnB = n0 + lrow;
    const int szA = (gmA < M) ? 16 : 0;
    const int szB = (gnB < N) ? 16 : 0;
    const int rA = (gmA < M) ? gmA : 0;
    const int rB = (gnB < N) ? gnB : 0;
    const uint32_t doff = (uint32_t)(lrow*SROW + lcol) * 2u;

    const int niter = K / KC;

    {
        uint32_t st = smb;
        cpa16(st + 0*TILE_B + doff,      Ahg + (size_t)rA*K + lcol,      szA);
        cpa16(st + 0*TILE_B + doff + 16, Ahg + (size_t)rA*K + lcol + 8,  szA);
        cpa16(st + 1*TILE_B + doff,      Alg + (size_t)rA*K + lcol,      szA);
        cpa16(st + 1*TILE_B + doff + 16, Alg + (size_t)rA*K + lcol + 8,  szA);
        cpa16(st + 2*TILE_B + doff,      Bhg + (size_t)rB*K + lcol,      szB);
        cpa16(st + 2*TILE_B + doff + 16, Bhg + (size_t)rB*K + lcol + 8,  szB);
        cpa16(st + 3*TILE_B + doff,      Blg + (size_t)rB*K + lcol,      szB);
        cpa16(st + 3*TILE_B + doff + 16, Blg + (size_t)rB*K + lcol + 8,  szB);
        cpa_commit();
    }

    for (int it = 0; it < niter; it++) {
        if (it + 1 < niter) {
            const int k0 = (it + 1) * KC;
            uint32_t st = smb + ((it + 1) & 1) * STAGE_B;
            cpa16(st + 0*TILE_B + doff,      Ahg + (size_t)rA*K + k0 + lcol,      szA);
            cpa16(st + 0*TILE_B + doff + 16, Ahg + (size_t)rA*K + k0 + lcol + 8,  szA);
            cpa16(st + 1*TILE_B + doff,      Alg + (size_t)rA*K + k0 + lcol,      szA);
            cpa16(st + 1*TILE_B + doff + 16, Alg + (size_t)rA*K + k0 + lcol + 8,  szA);
            cpa16(st + 2*TILE_B + doff,      Bhg + (size_t)rB*K + k0 + lcol,      szB);
            cpa16(st + 2*TILE_B + doff + 16, Bhg + (size_t)rB*K + k0 + lcol + 8,  szB);
            cpa16(st + 3*TILE_B + doff,      Blg + (size_t)rB*K + k0 + lcol,      szB);
            cpa16(st + 3*TILE_B + doff + 16, Blg + (size_t)rB*K + k0 + lcol + 8,  szB);
            cpa_commit();
            cpa_wait1();
        } else {
            cpa_wait0();
        }
        __syncthreads();

        const char* stage = dynsm + (it & 1) * STAGE_B;
        const __nv_bfloat16* Ah = (const __nv_bfloat16*)(stage + 0*TILE_B);
        const __nv_bfloat16* Al = (const __nv_bfloat16*)(stage + 1*TILE_B);
        const __nv_bfloat16* Bh = (const __nv_bfloat16*)(stage + 2*TILE_B);
        const __nv_bfloat16* Bl = (const __nv_bfloat16*)(stage + 3*TILE_B);

        #pragma unroll
        for (int pass = 0; pass < 3; pass++) {
            const __nv_bfloat16* Asrc = (pass == 2) ? Al : Ah;
            const __nv_bfloat16* Bsrc = (pass == 1) ? Bl : Bh;
            #pragma unroll
            for (int kk = 0; kk < KC; kk += 16) {
                uint32_t bf[4][2];
                #pragma unroll
                for (int nf = 0; nf < 4; nf++) {
                    int nrow = wn*32 + nf*8 + (lid >> 2);
                    int kcol = kk + (lid & 3)*2;
                    bf[nf][0] = *(const uint32_t*)&Bsrc[nrow*SROW + kcol];
                    bf[nf][1] = *(const uint32_t*)&Bsrc[nrow*SROW + kcol + 8];
                }
                #pragma unroll
                for (int mf = 0; mf < 4; mf++) {
                    int mrow = wm*64 + mf*16 + (lid >> 2);
                    int kcol = kk + (lid & 3)*2;
                    uint32_t a0 = *(const uint32_t*)&Asrc[mrow*SROW + kcol];
                    uint32_t a1 = *(const uint32_t*)&Asrc[(mrow+8)*SROW + kcol];
                    uint32_t a2 = *(const uint32_t*)&Asrc[mrow*SROW + kcol + 8];
                    uint32_t a3 = *(const uint32_t*)&Asrc[(mrow+8)*SROW + kcol + 8];
                    #pragma unroll
                    for (int nf = 0; nf < 4; nf++)
                        mma16816(acc[mf][nf][0], acc[mf][nf][1], acc[mf][nf][2], acc[mf][nf][3],
                                 a0, a1, a2, a3, bf[nf][0], bf[nf][1]);
                }
            }
        }
        __syncthreads();
    }

    #pragma unroll
    for (int mf = 0; mf < 4; mf++) {
        #pragma unroll
        for (int nf = 0; nf < 4; nf++) {
            int gm = m0 + wm*64 + mf*16 + (lid >> 2);
            int gn = n0 + wn*32 + nf*8 + (lid & 3)*2;
            if (gn < N) {
                float b0 = 0.0f, b1 = 0.0f;
                if (bias) { b0 = bias[gn]; b1 = bias[gn+1]; }
                if (gm < M) {
                    float2 v = make_float2(acc[mf][nf][0] + b0, acc[mf][nf][1] + b1);
                    if (relu) { v.x = fmaxf(v.x, 0.f); v.y = fmaxf(v.y, 0.f); }
                    *(float2*)(out + (size_t)gm*N + gn) = v;
                }
                if (gm + 8 < M) {
                    float2 v = make_float2(acc[mf][nf][2] + b0, acc[mf][nf][3] + b1);
                    if (relu) { v.x = fmaxf(v.x, 0.f); v.y = fmaxf(v.y, 0.f); }
                    *(float2*)(out + (size_t)(gm+8)*N + gn) = v;
                }
            }
        }
    }
}

// ---------------- fused scores GEMM + partial logsumexp ----------------------
// scores = q @ ent^T; per CTA writes per-row (max, sum exp(x-max)) for its 128-col tile.
__global__ __launch_bounds__(256, 2)
void scores_lse_k(const unsigned short* __restrict__ Ahg, const unsigned short* __restrict__ Alg,
                  const unsigned short* __restrict__ Bhg, const unsigned short* __restrict__ Blg)
{
    extern __shared__ char dynsm[];
    const uint32_t smb = s2u(dynsm);
    __shared__ float sm_max[4][128];
    __shared__ float sm_sum[4][128];

    const int tid = threadIdx.x;
    const int wid = tid >> 5, lid = tid & 31;
    const int wm = wid & 1, wn = wid >> 1;
    const int m0 = blockIdx.y * 128, n0 = blockIdx.x * 128;
    const int M = B2, N = NE, K = HD;

    float acc[4][4][4];
    #pragma unroll
    for (int i = 0; i < 4; i++)
        #pragma unroll
        for (int j = 0; j < 4; j++)
            #pragma unroll
            for (int k = 0; k < 4; k++) acc[i][j][k] = 0.0f;

    const int lrow = tid >> 1;
    const int lcol = (tid & 1) * 16;
    const int gmA = m0 + lrow;
    const int gnB = n0 + lrow;
    const int szA = (gmA < M) ? 16 : 0;
    const int szB = (gnB < N) ? 16 : 0;
    const int rA = (gmA < M) ? gmA : 0;
    const int rB = (gnB < N) ? gnB : 0;
    const uint32_t doff = (uint32_t)(lrow*SROW + lcol) * 2u;

    const int niter = K / KC;

    {
        uint32_t st = smb;
        cpa16(st + 0*TILE_B + doff,      Ahg + (size_t)rA*K + lcol,      szA);
        cpa16(st + 0*TILE_B + doff + 16, Ahg + (size_t)rA*K + lcol + 8,  szA);
        cpa16(st + 1*TILE_B + doff,      Alg + (size_t)rA*K + lcol,      szA);
        cpa16(st + 1*TILE_B + doff + 16, Alg + (size_t)rA*K + lcol + 8,  szA);
        cpa16(st + 2*TILE_B + doff,      Bhg + (size_t)rB*K + lcol,      szB);
        cpa16(st + 2*TILE_B + doff + 16, Bhg + (size_t)rB*K + lcol + 8,  szB);
        cpa16(st + 3*TILE_B + doff,      Blg + (size_t)rB*K + lcol,      szB);
        cpa16(st + 3*TILE_B + doff + 16, Blg + (size_t)rB*K + lcol + 8,  szB);
        cpa_commit();
    }

    for (int it = 0; it < niter; it++) {
        if (it + 1 < niter) {
            const int k0 = (it + 1) * KC;
            uint32_t st = smb + ((it + 1) & 1) * STAGE_B;
            cpa16(st + 0*TILE_B + doff,      Ahg + (size_t)rA*K + k0 + lcol,      szA);
            cpa16(st + 0*TILE_B + doff + 16, Ahg + (size_t)rA*K + k0 + lcol + 8,  szA);
            cpa16(st + 1*TILE_B + doff,      Alg + (size_t)rA*K + k0 + lcol,      szA);
            cpa16(st + 1*TILE_B + doff + 16, Alg + (size_t)rA*K + k0 + lcol + 8,  szA);
            cpa16(st + 2*TILE_B + doff,      Bhg + (size_t)rB*K + k0 + lcol,      szB);
            cpa16(st + 2*TILE_B + doff + 16, Bhg + (size_t)rB*K + k0 + lcol + 8,  szB);
            cpa16(st + 3*TILE_B + doff,      Blg + (size_t)rB*K + k0 + lcol,      szB);
            cpa16(st + 3*TILE_B + doff + 16, Blg + (size_t)rB*K + k0 + lcol + 8,  szB);
            cpa_commit();
            cpa_wait1();
        } else {
            cpa_wait0();
        }
        __syncthreads();

        const char* stage = dynsm + (it & 1) * STAGE_B;
        const __nv_bfloat16* Ah = (const __nv_bfloat16*)(stage + 0*TILE_B);
        const __nv_bfloat16* Al = (const __nv_bfloat16*)(stage + 1*TILE_B);
        const __nv_bfloat16* Bh = (const __nv_bfloat16*)(stage + 2*TILE_B);
        const __nv_bfloat16* Bl = (const __nv_bfloat16*)(stage + 3*TILE_B);

        #pragma unroll
        for (int pass = 0; pass < 3; pass++) {
            const __nv_bfloat16* Asrc = (pass == 2) ? Al : Ah;
            const __nv_bfloat16* Bsrc = (pass == 1) ? Bl : Bh;
            #pragma unroll
            for (int kk = 0; kk < KC; kk += 16) {
                uint32_t bf[4][2];
                #pragma unroll
                for (int nf = 0; nf < 4; nf++) {
                    int nrow = wn*32 + nf*8 + (lid >> 2);
                    int kcol = kk + (lid & 3)*2;
                    bf[nf][0] = *(const uint32_t*)&Bsrc[nrow*SROW + kcol];
                    bf[nf][1] = *(const uint32_t*)&Bsrc[nrow*SROW + kcol + 8];
                }
                #pragma unroll
                for (int mf = 0; mf < 4; mf++) {
                    int mrow = wm*64 + mf*16 + (lid >> 2);
                    int kcol = kk + (lid & 3)*2;
                    uint32_t a0 = *(const uint32_t*)&Asrc[mrow*SROW + kcol];
                    uint32_t a1 = *(const uint32_t*)&Asrc[(mrow+8)*SROW + kcol];
                    uint32_t a2 = *(const uint32_t*)&Asrc[mrow*SROW + kcol + 8];
                    uint32_t a3 = *(const uint32_t*)&Asrc[(mrow+8)*SROW + kcol + 8];
                    #pragma unroll
                    for (int nf = 0; nf < 4; nf++)
                        mma16816(acc[mf][nf][0], acc[mf][nf][1], acc[mf][nf][2], acc[mf][nf][3],
                                 a0, a1, a2, a3, bf[nf][0], bf[nf][1]);
                }
            }
        }
        __syncthreads();
    }

    // ---- epilogue: per-row tile (max, sumexp) with FFMA-only exp ----
    bool cval[4][2];
    #pragma unroll
    for (int nf = 0; nf < 4; nf++) {
        int gn = n0 + wn*32 + nf*8 + (lid & 3)*2;
        cval[nf][0] = gn < NE;
        cval[nf][1] = gn + 1 < NE;
    }
    #pragma unroll
    for (int h = 0; h < 2; h++) {   // row gm (h=0) and gm+8 (h=1)
        #pragma unroll
        for (int mf = 0; mf < 4; mf++) {
            float rm = -1e30f;
            #pragma unroll
            for (int nf = 0; nf < 4; nf++) {
                float v0 = cval[nf][0] ? acc[mf][nf][h*2+0] : -1e30f;
                float v1 = cval[nf][1] ? acc[mf][nf][h*2+1] : -1e30f;
                rm = fmaxf(rm, fmaxf(v0, v1));
            }
            rm = fmaxf(rm, __shfl_xor_sync(0xffffffffu, rm, 1));
            rm = fmaxf(rm, __shfl_xor_sync(0xffffffffu, rm, 2));
            float rs = 0.0f;
            #pragma unroll
            for (int nf = 0; nf < 4; nf++) {
                if (cval[nf][0]) rs += fexp(acc[mf][nf][h*2+0] - rm);
                if (cval[nf][1]) rs += fexp(acc[mf][nf][h*2+1] - rm);
            }
            rs += __shfl_xor_sync(0xffffffffu, rs, 1);
            rs += __shfl_xor_sync(0xffffffffu, rs, 2);
            if ((lid & 3) == 0) {
                int row = wm*64 + mf*16 + (lid >> 2) + h*8;  // 0..127
                sm_max[wn][row] = rm;
                sm_sum[wn][row] = rs;
            }
        }
    }
    __syncthreads();
    if (tid < 128) {
        int gm = m0 + tid;
        if (gm < B2) {
            float m = fmaxf(fmaxf(sm_max[0][tid], sm_max[1][tid]),
                            fmaxf(sm_max[2][tid], sm_max[3][tid]));
            float s = sm_sum[0][tid] * fexp(sm_max[0][tid] - m)
                    + sm_sum[1][tid] * fexp(sm_max[1][tid] - m)
                    + sm_sum[2][tid] * fexp(sm_max[2][tid] - m)
                    + sm_sum[3][tid] * fexp(sm_max[3][tid] - m);
            g_pmax[(size_t)gm*NTL + blockIdx.x] = m;
            g_psum[(size_t)gm*NTL + blockIdx.x] = s;
        }
    }
}

// ---------------- final NLL: merge partials + exact fp32 target dot ----------
__global__ void nll_k(const void* tt) {
    int b = blockIdx.x;
    int tx = threadIdx.x;  // 256
    __shared__ float sm[256];
    float pm = (tx < NTL) ? g_pmax[(size_t)b*NTL + tx] : -1e30f;
    sm[tx] = pm; __syncthreads();
    for (int o = 128; o; o >>= 1) { if (tx < o) sm[tx] = fmaxf(sm[tx], sm[tx+o]); __syncthreads(); }
    float M = sm[0];
    __syncthreads();
    float s = (tx < NTL) ? g_psum[(size_t)b*NTL + tx] * expf(pm - M) : 0.0f;
    sm[tx] = s; __syncthreads();
    for (int o = 128; o; o >>= 1) { if (tx < o) sm[tx] += sm[tx+o]; __syncthreads(); }
    float S = sm[0];
    __syncthreads();
    int tgt = (b < NT) ? ldix(tt, 3LL*b + 2) : ldix(tt, 3LL*(b - NT));
    float d = 0.0f;
    for (int i = tx; i < HD; i += 256) d += g_q[(size_t)b*HD + i] * g_ent[(size_t)tgt*HD + i];
    sm[tx] = d; __syncthreads();
    for (int o = 128; o; o >>= 1) { if (tx < o) sm[tx] += sm[tx+o]; __syncthreads(); }
    if (tx == 0) g_nll[b] = M + logf(S) - sm[0];
}

// ---------------- GRU elementwise update ----------------
__global__ void gru_k() {
    int i = blockIdx.x*blockDim.x + threadIdx.x;
    if (i >= R2*64) return;
    int row = i >> 6, c = (i & 63) * 4;
    const float* gi = g_gi + (size_t)row*768;
    const float* gh = g_gh + (size_t)row*768;
    float4 ir = *(const float4*)(gi + c);
    float4 iz = *(const float4*)(gi + 256 + c);
    float4 in_ = *(const float4*)(gi + 512 + c);
    float4 hr = *(const float4*)(gh + c);
    float4 hz = *(const float4*)(gh + 256 + c);
    float4 hn = *(const float4*)(gh + 512 + c);
    float4 h = ((const float4*)g_rel)[i];
    float4 o;
    {
        float r = sigf(ir.x + hr.x), z = sigf(iz.x + hz.x);
        float n = tanhf(in_.x + r*hn.x);
        o.x = (1.0f - z)*n + z*h.x;
    }
    {
        float r = sigf(ir.y + hr.y), z = sigf(iz.y + hz.y);
        float n = tanhf(in_.y + r*hn.y);
        o.y = (1.0f - z)*n + z*h.y;
    }
    {
        float r = sigf(ir.z + hr.z), z = sigf(iz.z + hz.z);
        float n = tanhf(in_.z + r*hn.z);
        o.z = (1.0f - z)*n + z*h.z;
    }
    {
        float r = sigf(ir.w + hr.w), z = sigf(iz.w + hz.w);
        float n = tanhf(in_.w + r*hn.w);
        o.w = (1.0f - z)*n + z*h.w;
    }
    ((float4*)g_rel)[i] = o;
}

// ---------------- edge message scatter ----------------
__global__ void edge_scatter_k(const void* esrc, const void* erel, const void* edst, long long off) {
    long long idx = (long long)blockIdx.x*4 + (threadIdx.x >> 6);
    int lane = threadIdx.x & 63;
    if (idx < EE) {
        int s = ldix(esrc, off + idx);
        int r = ldix(erel, off + idx);
        int d = ldix(edst, off + idx);
        float4 a = ((const float4*)(g_entW + (size_t)s*HD))[lane];
        float4 b = ((const float4*)(g_relW + (size_t)r*HD))[lane];
        float4 v = make_float4(a.x+b.x, a.y+b.y, a.z+b.z, a.w+b.w);
        red4(g_agg + (size_t)d*HD + lane*4, v);
        if (lane == 0) atomicAdd(&g_cnt[d], 1.0f);
    }
}

// ---------------- gated entity update ----------------
__global__ void entupd_k() {
    int i = blockIdx.x*blockDim.x + threadIdx.x;
    if (i >= NE*64) return;
    int row = i >> 6;
    float inv = 1.0f / fmaxf(g_cnt[row], 1.0f);
    float4 a = ((const float4*)g_agg)[i];
    float4 cur = make_float4(fmaxf(a.x*inv, 0.f), fmaxf(a.y*inv, 0.f),
                             fmaxf(a.z*inv, 0.f), fmaxf(a.w*inv, 0.f));
    float4 tl = ((const float4*)g_twl)[i];
    float4 tw = make_float4(sigf(tl.x), sigf(tl.y), sigf(tl.z), sigf(tl.w));
    float4 e = ((const float4*)g_ent)[i];
    e.x = tw.x*cur.x + (1.0f - tw.x)*e.x;
    e.y = tw.y*cur.y + (1.0f - tw.y)*e.y;
    e.z = tw.z*cur.z + (1.0f - tw.z)*e.z;
    e.w = tw.w*cur.w + (1.0f - tw.w)*e.w;
    ((float4*)g_ent)[i] = e;
}

// ---------------- hypergraph scatter: y[row] += val * x[col] ----------------
__global__ void hyper_scatter_k(const float* x, float* y, const void* rows,
                                const void* cols, const float* val, int nnz) {
    long long idx = (long long)blockIdx.x*4 + (threadIdx.x >> 6);
    int lane = threadIdx.x & 63;
    if (idx < nnz) {
        int r = ldix(rows, idx);
        int c = ldix(cols, idx);
        float vl = val[idx];
        float4 v = ((const float4*)(x + (size_t)c*HD))[lane];
        v.x *= vl; v.y *= vl; v.z *= vl; v.w *= vl;
        red4(y + (size_t)r*HD + lane*4, v);
    }
}

// ---------------- x += l2norm(y) (per-row) ----------------
__global__ void l2add_k(float* x, const float* y) {
    int row = blockIdx.x;
    int lane = threadIdx.x;  // 64
    float4 yv = ((const float4*)(y + (size_t)row*HD))[lane];
    float ss = yv.x*yv.x + yv.y*yv.y + yv.z*yv.z + yv.w*yv.w;
    #pragma unroll
    for (int o = 16; o; o >>= 1) ss += __shfl_xor_sync(0xffffffffu, ss, o);
    __shared__ float s2[2];
    if ((lane & 31) == 0) s2[lane >> 5] = ss;
    __syncthreads();
    float nrm = sqrtf(s2[0] + s2[1]);
    float sc = 1.0f / fmaxf(nrm, 1e-12f);
    float4 xv = ((float4*)(x + (size_t)row*HD))[lane];
    xv.x += yv.x*sc; xv.y += yv.y*sc; xv.z += yv.z*sc; xv.w += yv.w*sc;
    ((float4*)(x + (size_t)row*HD))[lane] = xv;
}

// ---------------- conv1d (C_in=3, k=3, pad=1) + relu -> bf16 hi/lo ------------
__global__ void conv_k(const void* tt, const float* __restrict__ sent,
                       const float* __restrict__ cw, const float* __restrict__ cb) {
    int b = blockIdx.x;
    int t = threadIdx.x;  // 256 = HD
    __shared__ float sf[3][HD+2];
    __shared__ float sw[CH*9];
    __shared__ float sb[CH];
    int a0, a1, srow;
    if (b < NT) { a0 = ldix(tt, 3LL*b); a1 = ldix(tt, 3LL*b + 1); srow = b; }
    else { int i = b - NT; a0 = ldix(tt, 3LL*i + 2); a1 = ldix(tt, 3LL*i + 1) + NR; srow = i; }
    sf[0][t+1] = g_ent[(size_t)a0*HD + t];
    sf[1][t+1] = g_rel[(size_t)a1*HD + t];
    sf[2][t+1] = sent[(size_t)srow*HD + t];
    if (t < 3) { sf[t][0] = 0.0f; sf[t][HD+1] = 0.0f; }
    for (int i = t; i < CH*9; i += blockDim.x) sw[i] = cw[i];
    if (t < CH) sb[t] = cb[t];
    __syncthreads();
    float v00 = sf[0][t], v01 = sf[0][t+1], v02 = sf[0][t+2];
    float v10 = sf[1][t], v11 = sf[1][t+1], v12 = sf[1][t+2];
    float v20 = sf[2][t], v21 = sf[2][t+1], v22 = sf[2][t+2];
    size_t base = (size_t)b*CH*HD;
    #pragma unroll 5
    for (int ch = 0; ch < CH; ch++) {
        const float* w = sw + ch*9;
        float acc = sb[ch];
        acc += v00*w[0] + v01*w[1] + v02*w[2];
        acc += v10*w[3] + v11*w[4] + v12*w[5];
        acc += v20*w[6] + v21*w[7] + v22*w[8];
        acc = fmaxf(acc, 0.0f);
        __nv_bfloat16 h = __float2bfloat16(acc);
        ((__nv_bfloat16*)g_convh)[base + ch*HD + t] = h;
        ((__nv_bfloat16*)g_convl)[base + ch*HD + t] = __float2bfloat16(acc - __bfloat162float(h));
    }
}

__global__ void mean_k(float* out) {
    __shared__ float sm[256];
    float s = 0.0f;
    for (int i = threadIdx.x; i < B2; i += 256) s += g_nll[i];
    sm[threadIdx.x] = s; __syncthreads();
    for (int o = 128; o; o >>= 1) { if (threadIdx.x < o) sm[threadIdx.x] += sm[threadIdx.x+o]; __syncthreads(); }
    if (threadIdx.x == 0) out[0] = sm[0] / (float)B2;
}

// ---------------- host orchestration ----------------
static void mgemm(const unsigned short* Ah, const unsigned short* Al,
                  const unsigned short* Bh, const unsigned short* Bl,
                  const float* bias, float* C, int M, int N, int K, bool relu) {
    dim3 g((N + 127)/128, (M + 127)/128);
    mma_gemm_k<<<g, 256, 2*STAGE_B>>>(Ah, Al, Bh, Bl, bias, C, M, N, K, relu ? 1 : 0);
}

extern "C" void kernel_launch(void* const* d_in, const int* in_sizes, int n_in,
                              void* d_out, int out_size) {
    const float* dyn_emb = (const float*)d_in[0];
    const float* emb_rel = (const float*)d_in[1];
    const float* W_ih   = (const float*)d_in[2];
    const float* W_hh   = (const float*)d_in[3];
    const float* b_ih   = (const float*)d_in[4];
    const float* b_hh   = (const float*)d_in[5];
    const float* agg_W  = (const float*)d_in[6];
    const float* tg_W   = (const float*)d_in[7];
    const float* tg_b   = (const float*)d_in[8];
    const float* hev    = (const float*)d_in[9];
    const float* hrv    = (const float*)d_in[10];
    const float* conv_w = (const float*)d_in[11];
    const float* conv_b = (const float*)d_in[12];
    const float* fc_W   = (const float*)d_in[13];
    const float* fc_b   = (const float*)d_in[14];
    const float* sent   = (const float*)d_in[15];
    const void* esrc = d_in[16];
    const void* erel = d_in[17];
    const void* edst = d_in[18];
    const void* rte  = d_in[19];
    const void* rids = d_in[20];
    const void* her  = d_in[21];
    const void* hec  = d_in[22];
    const void* hrr  = d_in[23];
    const void* hrc  = d_in[24];
    const void* ttp  = d_in[25];

    float *p_ent, *p_rel, *p_xsum, *p_xcnt, *p_gi, *p_gh, *p_entW, *p_relW,
          *p_agg, *p_cnt, *p_twl, *p_y, *p_yrel, *p_q, *p_xin;
    unsigned short *p_qh, *p_ql, *p_eh, *p_el, *p_convh, *p_convl,
                   *p_xinh, *p_xinl, *p_relh, *p_rell,
                   *p_wihh, *p_wihl, *p_whhh, *p_whhl,
                   *p_aggth, *p_aggtl, *p_tgth, *p_tgtl, *p_fcth, *p_fctl;
    cudaGetSymbolAddress((void**)&p_ent,  g_ent);
    cudaGetSymbolAddress((void**)&p_rel,  g_rel);
    cudaGetSymbolAddress((void**)&p_xsum, g_xsum);
    cudaGetSymbolAddress((void**)&p_xcnt, g_xcnt);
    cudaGetSymbolAddress((void**)&p_xin,  g_xin);
    cudaGetSymbolAddress((void**)&p_gi,   g_gi);
    cudaGetSymbolAddress((void**)&p_gh,   g_gh);
    cudaGetSymbolAddress((void**)&p_entW, g_entW);
    cudaGetSymbolAddress((void**)&p_relW, g_relW);
    cudaGetSymbolAddress((void**)&p_agg,  g_agg);
    cudaGetSymbolAddress((void**)&p_cnt,  g_cnt);
    cudaGetSymbolAddress((void**)&p_twl,  g_twl);
    cudaGetSymbolAddress((void**)&p_y,    g_y);
    cudaGetSymbolAddress((void**)&p_yrel, g_yrel);
    cudaGetSymbolAddress((void**)&p_q,    g_q);
    cudaGetSymbolAddress((void**)&p_qh, g_qh);
    cudaGetSymbolAddress((void**)&p_ql, g_ql);
    cudaGetSymbolAddress((void**)&p_eh, g_eh);
    cudaGetSymbolAddress((void**)&p_el, g_el);
    cudaGetSymbolAddress((void**)&p_convh, g_convh);
    cudaGetSymbolAddress((void**)&p_convl, g_convl);
    cudaGetSymbolAddress((void**)&p_xinh, g_xinh);
    cudaGetSymbolAddress((void**)&p_xinl, g_xinl);
    cudaGetSymbolAddress((void**)&p_relh, g_relh);
    cudaGetSymbolAddress((void**)&p_rell, g_rell);
    cudaGetSymbolAddress((void**)&p_wihh, g_wihh);
    cudaGetSymbolAddress((void**)&p_wihl, g_wihl);
    cudaGetSymbolAddress((void**)&p_whhh, g_whhh);
    cudaGetSymbolAddress((void**)&p_whhl, g_whhl);
    cudaGetSymbolAddress((void**)&p_aggth, g_aggth);
    cudaGetSymbolAddress((void**)&p_aggtl, g_aggtl);
    cudaGetSymbolAddress((void**)&p_tgth, g_tgth);
    cudaGetSymbolAddress((void**)&p_tgtl, g_tgtl);
    cudaGetSymbolAddress((void**)&p_fcth, g_fcth);
    cudaGetSymbolAddress((void**)&p_fctl, g_fctl);

    cudaFuncSetAttribute(mma_gemm_k, cudaFuncAttributeMaxDynamicSharedMemorySize, 2*STAGE_B);
    cudaFuncSetAttribute(scores_lse_k, cudaFuncAttributeMaxDynamicSharedMemorySize, 2*STAGE_B);

    detect_k<<<1, 32>>>(esrc);
    copy_k<<<(NE*HD + 255)/256, 256>>>(p_ent, dyn_emb, NE*HD);
    copy_k<<<(R2*HD + 255)/256, 256>>>(p_rel, emb_rel, R2*HD);

    // weight preprocessing (once): split / transpose-split to bf16 hi/lo
    split_k<<<(3*HD*2*HD + 255)/256, 256>>>(W_ih, p_wihh, p_wihl, 3*HD*2*HD);
    split_k<<<(3*HD*HD + 255)/256, 256>>>(W_hh, p_whhh, p_whhl, 3*HD*HD);
    tsplit_k<<<(HD*HD + 255)/256, 256>>>(agg_W, p_aggth, p_aggtl, HD, HD);
    tsplit_k<<<(HD*HD + 255)/256, 256>>>(tg_W, p_tgth, p_tgtl, HD, HD);
    tsplit_k<<<(CH*HD*HD + 255)/256, 256>>>(fc_W, p_fcth, p_fctl, CH*HD, HD);

    for (int t = 0; t < TT; t++) {
        zero_k<<<(NREP*R2*HD + 255)/256, 256>>>(p_xsum, NREP*R2*HD);
        zero_k<<<(R2 + 255)/256, 256>>>(p_xcnt, R2);
        hist_k<<<128, 256>>>(rids, (long long)t*MM, MM);
        seg_scatter_k<<<(MM + 3)/4, 256>>>(rte, rids, (long long)t*MM);
        xin_k<<<(R2*128 + 255)/256, 256>>>();

        // GRU gates via mma
        split_k<<<(R2*2*HD + 255)/256, 256>>>(p_xin, p_xinh, p_xinl, R2*2*HD);
        split_k<<<(R2*HD + 255)/256, 256>>>(p_rel, p_relh, p_rell, R2*HD);
        mgemm(p_xinh, p_xinl, p_wihh, p_wihl, b_ih, p_gi, R2, 3*HD, 2*HD, false);
        mgemm(p_relh, p_rell, p_whhh, p_whhl, b_hh, p_gh, R2, 3*HD, HD, false);
        gru_k<<<(R2*64 + 255)/256, 256>>>();

        // entW = ent @ agg_W ; relW = rel @ agg_W (rel is post-GRU: re-split)
        split_k<<<(NE*HD + 255)/256, 256>>>(p_ent, p_eh, p_el, NE*HD);
        split_k<<<(R2*HD + 255)/256, 256>>>(p_rel, p_relh, p_rell, R2*HD);
        mgemm(p_eh, p_el, p_aggth, p_aggtl, nullptr, p_entW, NE, HD, HD, false);
        mgemm(p_relh, p_rell, p_aggth, p_aggtl, nullptr, p_relW, R2, HD, HD, false);

        zero_k<<<(NE*HD + 255)/256, 256>>>(p_agg, NE*HD);
        zero_k<<<(NE + 255)/256, 256>>>(p_cnt, NE);
        edge_scatter_k<<<(EE + 3)/4, 256>>>(esrc, erel, edst, (long long)t*EE);

        // twl = ent @ tg_W + tg_b (same ent split)
        mgemm(p_eh, p_el, p_tgth, p_tgtl, tg_b, p_twl, NE, HD, HD, false);
        entupd_k<<<(NE*64 + 255)/256, 256>>>();
    }

    for (int l = 0; l < 2; l++) {
        zero_k<<<(NE*HD + 255)/256, 256>>>(p_y, NE*HD);
        hyper_scatter_k<<<(NNZE + 3)/4, 256>>>(p_ent, p_y, her, hec, hev, NNZE);
        l2add_k<<<NE, 64>>>(p_ent, p_y);
    }
    for (int l = 0; l < 2; l++) {
        zero_k<<<(R2*HD + 255)/256, 256>>>(p_yrel, R2*HD);
        hyper_scatter_k<<<(NNZR + 3)/4, 256>>>(p_rel, p_yrel, hrr, hrc, hrv, NNZR);
        l2add_k<<<R2, 64>>>(p_rel, p_yrel);
    }

    // final ent split for scores
    split_k<<<(NE*HD + 255)/256, 256>>>(p_ent, p_eh, p_el, NE*HD);

    conv_k<<<B2, 256>>>(ttp, sent, conv_w, conv_b);
    mgemm(p_convh, p_convl, p_fcth, p_fctl, fc_b, p_q, B2, HD, CH*HD, true);
    split_k<<<(B2*HD + 255)/256, 256>>>(p_q, p_qh, p_ql, B2*HD);

    // fused scores GEMM + partial logsumexp (no 320MB scores buffer)
    scores_lse_k<<<dim3(NTL, (B2 + 127)/128), 256, 2*STAGE_B>>>(p_qh, p_ql, p_eh, p_el);

    nll_k<<<B2, 256>>>(ttp);
    mean_k<<<1, 256>>>((float*)d_out);
}